// round 8
// baseline (speedup 1.0000x reference)
#include <cuda_runtime.h>
#include <cuda_fp16.h>
#include <cstdint>

// ---------------------------------------------------------------------------
// Problem constants
// ---------------------------------------------------------------------------
#define HIDDEN   1024
#define FRAMES   16
#define SPATIAL  1024
#define BATCH    2
#define NSEQ     (BATCH*SPATIAL)        // 2048
#define TOKENS   (BATCH*FRAMES*SPATIAL) // 32768
#define NH       16
#define HD       64
#define QKV_N    3072

// ---------------------------------------------------------------------------
// Scratch
// ---------------------------------------------------------------------------
__device__ __half g_xh [(size_t)TOKENS * HIDDEN];  // LN'd + transposed, fp16
__device__ __half g_wqh[(size_t)QKV_N  * HIDDEN];  // w_qkv fp16
__device__ __half g_woh[(size_t)HIDDEN * HIDDEN];  // w_out fp16
__device__ __half g_ah [(size_t)TOKENS * HIDDEN];  // attn out fp16, final order
__device__ __half g_qkv[(size_t)TOKENS * QKV_N];   // QKV fp16

// ---------------------------------------------------------------------------
// PTX helpers
// ---------------------------------------------------------------------------
__device__ __forceinline__ uint32_t smem_u32(const void* p) {
    uint32_t a;
    asm("{ .reg .u64 t; cvta.to.shared.u64 t, %1; cvt.u32.u64 %0, t; }" : "=r"(a) : "l"(p));
    return a;
}
__device__ __forceinline__ void cp16(uint32_t dst, const void* src) {
    asm volatile("cp.async.cg.shared.global [%0], [%1], 16;" :: "r"(dst), "l"(src));
}
#define CP_COMMIT() asm volatile("cp.async.commit_group;" ::: "memory")
#define CP_WAIT2()  asm volatile("cp.async.wait_group 2;" ::: "memory")

__device__ __forceinline__ void ldmx4(uint32_t addr, uint32_t* r) {
    asm volatile("ldmatrix.sync.aligned.m8n8.x4.shared.b16 {%0,%1,%2,%3}, [%4];"
        : "=r"(r[0]), "=r"(r[1]), "=r"(r[2]), "=r"(r[3]) : "r"(addr));
}
__device__ __forceinline__ void mma_f16(float* d, const uint32_t* a, const uint32_t* b) {
    asm volatile("mma.sync.aligned.m16n8k16.row.col.f32.f16.f16.f32 "
        "{%0,%1,%2,%3},{%4,%5,%6,%7},{%8,%9},{%0,%1,%2,%3};"
        : "+f"(d[0]), "+f"(d[1]), "+f"(d[2]), "+f"(d[3])
        : "r"(a[0]), "r"(a[1]), "r"(a[2]), "r"(a[3]), "r"(b[0]), "r"(b[1]));
}

// byte offset of 16B chunk (r, ch) in a [rows x 64B] tile, XOR-swizzled
__device__ __forceinline__ uint32_t toff(int r, int ch) {
    return (uint32_t)(r * 64 + ((ch ^ ((r >> 1) & 3)) << 4));
}

// ---------------------------------------------------------------------------
// Kernel 1: LayerNorm + temporal transpose -> fp16
// ---------------------------------------------------------------------------
__global__ __launch_bounds__(256) void ln_transpose_kernel(
    const float* __restrict__ x,
    const float* __restrict__ gamma,
    const float* __restrict__ beta)
{
    const int token = blockIdx.x;
    const int b  = token >> 14;
    const int sg = token & 16383;
    const int t  = sg >> 10;
    const int s  = sg & 1023;

    const int tid = threadIdx.x;
    const float4 v = ((const float4*)(x + (size_t)token * HIDDEN))[tid];

    float sum = v.x + v.y + v.z + v.w;
    float sq  = v.x*v.x + v.y*v.y + v.z*v.z + v.w*v.w;

    #pragma unroll
    for (int o = 16; o > 0; o >>= 1) {
        sum += __shfl_xor_sync(0xffffffffu, sum, o);
        sq  += __shfl_xor_sync(0xffffffffu, sq,  o);
    }
    __shared__ float s_sum[8], s_sq[8];
    __shared__ float s_mu, s_rstd;
    if ((tid & 31) == 0) { s_sum[tid >> 5] = sum; s_sq[tid >> 5] = sq; }
    __syncthreads();
    if (tid == 0) {
        float ts = 0.f, tq = 0.f;
        #pragma unroll
        for (int i = 0; i < 8; ++i) { ts += s_sum[i]; tq += s_sq[i]; }
        const float mu  = ts * (1.0f / HIDDEN);
        const float var = tq * (1.0f / HIDDEN) - mu * mu;
        s_mu = mu;
        s_rstd = rsqrtf(var + 1e-5f);
    }
    __syncthreads();
    const float mu = s_mu, rs = s_rstd;

    const float4 g  = ((const float4*)gamma)[tid];
    const float4 be = ((const float4*)beta)[tid];
    __half h[4];
    h[0] = __float2half_rn((v.x - mu) * rs * g.x + be.x);
    h[1] = __float2half_rn((v.y - mu) * rs * g.y + be.y);
    h[2] = __float2half_rn((v.z - mu) * rs * g.z + be.z);
    h[3] = __float2half_rn((v.w - mu) * rs * g.w + be.w);

    const size_t orow = (size_t)(b * SPATIAL + s) * FRAMES + t;
    *(uint2*)(g_xh + orow * HIDDEN + 4 * tid) = *(uint2*)h;
}

// ---------------------------------------------------------------------------
// fp32 -> fp16 weight convert
// ---------------------------------------------------------------------------
__global__ __launch_bounds__(256) void w2h_kernel(
    const float* __restrict__ w, __half* __restrict__ wh, int total)
{
    const int idx = (blockIdx.x * 256 + threadIdx.x) * 4;
    if (idx >= total) return;
    const float4 v = *(const float4*)(w + idx);
    __half h[4] = { __float2half_rn(v.x), __float2half_rn(v.y),
                    __float2half_rn(v.z), __float2half_rn(v.w) };
    *(uint2*)(wh + idx) = *(uint2*)h;
}

// ---------------------------------------------------------------------------
// fp16 mma.sync GEMM: C[M,N] = A[M,1024] * B[N,1024]^T
// BM=128, BN=256, BK=32; 256 threads (8 warps 2x4, warp tile 64x64);
// 4-stage cp.async ring, one __syncthreads per chunk, load-first schedule.
// Output type templated (fp16 for QKV, fp32 for final projection).
// ---------------------------------------------------------------------------
#define KCH 32                    // 1024 / 32
#define A_STG 8192                // 128*32*2
#define B_STG 16384               // 256*32*2
#define STG   (A_STG + B_STG)     // 24576
#define GEMM_SMEM (4 * STG)       // 98304

template <typename OutT>
__global__ __launch_bounds__(256, 1) void gemm_f16(
    const __half* __restrict__ A,
    const __half* __restrict__ B,
    OutT* __restrict__ C, int N)
{
    extern __shared__ __half smem[];
    const uint32_t base = smem_u32(smem);

    const int tid  = threadIdx.x;
    const int lane = tid & 31;
    const int wid  = tid >> 5;
    const int wm   = wid >> 2;         // 0..1  (64-row slab)
    const int wn   = wid & 3;          // 0..3  (64-col slab)
    const int bm   = blockIdx.y * 128;
    const int bn   = blockIdx.x * 256;

    // staging: 1536 16B chunks/stage, 6 per thread (A rows sr,sr+64; B rows sr..+192)
    const int sr = tid >> 2;           // 0..63
    const int sc = tid & 3;
    const char* aSrc0 = (const char*)(A + (size_t)(bm + sr) * HIDDEN) + sc * 16;
    const char* aSrc1 = (const char*)(A + (size_t)(bm + sr + 64) * HIDDEN) + sc * 16;
    const char* bSrc0 = (const char*)(B + (size_t)(bn + sr) * HIDDEN) + sc * 16;
    const char* bSrc1 = (const char*)(B + (size_t)(bn + sr + 64) * HIDDEN) + sc * 16;
    const char* bSrc2 = (const char*)(B + (size_t)(bn + sr + 128) * HIDDEN) + sc * 16;
    const char* bSrc3 = (const char*)(B + (size_t)(bn + sr + 192) * HIDDEN) + sc * 16;
    const uint32_t aDst0 = base + toff(sr, sc);
    const uint32_t aDst1 = base + toff(sr + 64, sc);
    const uint32_t bDst0 = base + A_STG + toff(sr, sc);
    const uint32_t bDst1 = base + A_STG + toff(sr + 64, sc);
    const uint32_t bDst2 = base + A_STG + toff(sr + 128, sc);
    const uint32_t bDst3 = base + A_STG + toff(sr + 192, sc);

    #define LOAD(c)                                              \
    {                                                            \
        const uint32_t so = ((c) & 3) * STG;                     \
        const int koff = (c) * 64;                               \
        cp16(aDst0 + so, aSrc0 + koff);                          \
        cp16(aDst1 + so, aSrc1 + koff);                          \
        cp16(bDst0 + so, bSrc0 + koff);                          \
        cp16(bDst1 + so, bSrc1 + koff);                          \
        cp16(bDst2 + so, bSrc2 + koff);                          \
        cp16(bDst3 + so, bSrc3 + koff);                          \
    }

    // fragment smem offsets within a stage
    uint32_t a_off[4][2], b_off[4][2];
    #pragma unroll
    for (int mi = 0; mi < 4; ++mi)
        #pragma unroll
        for (int kk = 0; kk < 2; ++kk) {
            const int r  = wm * 64 + mi * 16 + (lane & 7) + ((lane >> 3) & 1) * 8;
            const int ch = kk * 2 + (lane >> 4);
            a_off[mi][kk] = toff(r, ch);
        }
    #pragma unroll
    for (int p = 0; p < 4; ++p)       // pairs of n8 tiles
        #pragma unroll
        for (int kk = 0; kk < 2; ++kk) {
            const int r  = wn * 64 + p * 16 + (lane & 7) + (lane >> 4) * 8;
            const int ch = kk * 2 + ((lane >> 3) & 1);
            b_off[p][kk] = A_STG + toff(r, ch);
        }

    float acc[4][8][4];
    #pragma unroll
    for (int i = 0; i < 4; ++i)
        #pragma unroll
        for (int j = 0; j < 8; ++j)
            #pragma unroll
            for (int e = 0; e < 4; ++e) acc[i][j][e] = 0.f;

    LOAD(0); CP_COMMIT();
    LOAD(1); CP_COMMIT();
    LOAD(2); CP_COMMIT();

    #pragma unroll 1
    for (int c = 0; c < KCH; ++c) {
        CP_WAIT2();
        __syncthreads();

        // issue next stage's DMA immediately (slot (c+3)&3 finished reads at c-1)
        if (c + 3 < KCH) LOAD(c + 3);
        CP_COMMIT();

        const uint32_t so = base + (c & 3) * STG;

        #pragma unroll
        for (int kk = 0; kk < 2; ++kk) {
            uint32_t bq[4][4];
            #pragma unroll
            for (int p = 0; p < 4; ++p) ldmx4(so + b_off[p][kk], bq[p]);
            #pragma unroll
            for (int mi = 0; mi < 4; ++mi) {
                uint32_t aq[4];
                ldmx4(so + a_off[mi][kk], aq);
                #pragma unroll
                for (int p = 0; p < 4; ++p) {
                    mma_f16(acc[mi][2*p],   aq, &bq[p][0]);
                    mma_f16(acc[mi][2*p+1], aq, &bq[p][2]);
                }
            }
        }
    }
    #undef LOAD

    // epilogue
    #pragma unroll
    for (int mi = 0; mi < 4; ++mi) {
        const int row = bm + wm * 64 + mi * 16 + (lane >> 2);
        #pragma unroll
        for (int nj = 0; nj < 8; ++nj) {
            const int col = bn + wn * 64 + nj * 8 + (lane & 3) * 2;
            if (sizeof(OutT) == 4) {
                float* Cf = (float*)C;
                *(float2*)(Cf + (size_t)row * N + col)       = make_float2(acc[mi][nj][0], acc[mi][nj][1]);
                *(float2*)(Cf + (size_t)(row + 8) * N + col) = make_float2(acc[mi][nj][2], acc[mi][nj][3]);
            } else {
                __half* Ch = (__half*)C;
                *(__half2*)(Ch + (size_t)row * N + col)       = __float22half2_rn(make_float2(acc[mi][nj][0], acc[mi][nj][1]));
                *(__half2*)(Ch + (size_t)(row + 8) * N + col) = __float22half2_rn(make_float2(acc[mi][nj][2], acc[mi][nj][3]));
            }
        }
    }
}

// ---------------------------------------------------------------------------
// Kernel 3: RoPE + causal attention (fp16 qkv in, fp16 out, final order)
// ---------------------------------------------------------------------------
__global__ __launch_bounds__(64) void attn_kernel()
{
    const int nb = blockIdx.x;
    const int n  = nb >> 4;
    const int hh = nb & 15;
    const int tid = threadIdx.x;

    __shared__ float qs[FRAMES][HD + 1];
    __shared__ float ks[FRAMES][HD + 1];
    __shared__ float vs[FRAMES][HD + 1];
    __shared__ float P [FRAMES][FRAMES + 1];

    const __half* bptr = g_qkv + (size_t)n * FRAMES * QKV_N + hh * HD;

    // half2 loads: 16 frames x 32 pairs
    for (int idx = tid; idx < FRAMES * 32; idx += 64) {
        const int t  = idx >> 5;
        const int dp = idx & 31;
        const __half* row = bptr + (size_t)t * QKV_N + 2 * dp;
        const float2 q = __half22float2(*(const __half2*)(row));
        const float2 k = __half22float2(*(const __half2*)(row + HIDDEN));
        const float2 v = __half22float2(*(const __half2*)(row + 2 * HIDDEN));
        qs[t][2*dp] = q.x; qs[t][2*dp+1] = q.y;
        ks[t][2*dp] = k.x; ks[t][2*dp+1] = k.y;
        vs[t][2*dp] = v.x; vs[t][2*dp+1] = v.y;
    }
    __syncthreads();

    for (int idx = tid; idx < FRAMES * 32; idx += 64) {
        const int t = idx >> 5;
        const int d = idx & 31;
        const float inv = __expf(-(float)d * 0.28782313662425576f);
        float sn, cs;
        __sincosf((float)t * inv, &sn, &cs);
        const float q1 = qs[t][d], q2 = qs[t][d + 32];
        qs[t][d]      = q1 * cs - q2 * sn;
        qs[t][d + 32] = q2 * cs + q1 * sn;
        const float k1 = ks[t][d], k2 = ks[t][d + 32];
        ks[t][d]      = k1 * cs - k2 * sn;
        ks[t][d + 32] = k2 * cs + k1 * sn;
    }
    __syncthreads();

    for (int idx = tid; idx < FRAMES * FRAMES; idx += 64) {
        const int i = idx >> 4;
        const int j = idx & 15;
        float v = -INFINITY;
        if (j <= i) {
            float acc = 0.f;
            #pragma unroll
            for (int d = 0; d < HD; ++d) acc += qs[i][d] * ks[j][d];
            v = acc * 0.125f;
        }
        P[i][j] = v;
    }
    __syncthreads();

    if (tid < FRAMES) {
        const int i = tid;
        float m = -INFINITY;
        for (int j = 0; j <= i; ++j) m = fmaxf(m, P[i][j]);
        float sum = 0.f;
        for (int j = 0; j <= i; ++j) { const float e = expf(P[i][j] - m); P[i][j] = e; sum += e; }
        const float r = 1.f / sum;
        for (int j = 0; j <= i; ++j) P[i][j] *= r;
        for (int j = i + 1; j < FRAMES; ++j) P[i][j] = 0.f;
    }
    __syncthreads();

    const int d = tid;
    const int b = n >> 10;
    const int s = n & 1023;
    #pragma unroll
    for (int i = 0; i < FRAMES; ++i) {
        float acc = 0.f;
        #pragma unroll
        for (int j = 0; j < FRAMES; ++j) acc += P[i][j] * vs[j][d];
        g_ah[(size_t)(b * 16384 + i * 1024 + s) * HIDDEN + hh * HD + d] = __float2half_rn(acc);
    }
}

// ---------------------------------------------------------------------------
// Launch
// ---------------------------------------------------------------------------
extern "C" void kernel_launch(void* const* d_in, const int* in_sizes, int n_in,
                              void* d_out, int out_size)
{
    const float* x      = (const float*)d_in[0];
    const float* w_qkv  = (const float*)d_in[1];
    const float* w_out  = (const float*)d_in[2];
    const float* gamma  = (const float*)d_in[3];
    const float* beta   = (const float*)d_in[4];
    float* out = (float*)d_out;

    __half *xh, *wqh, *woh, *ah, *qkv;
    cudaGetSymbolAddress((void**)&xh,  g_xh);
    cudaGetSymbolAddress((void**)&wqh, g_wqh);
    cudaGetSymbolAddress((void**)&woh, g_woh);
    cudaGetSymbolAddress((void**)&ah,  g_ah);
    cudaGetSymbolAddress((void**)&qkv, g_qkv);

    cudaFuncSetAttribute(gemm_f16<__half>, cudaFuncAttributeMaxDynamicSharedMemorySize, GEMM_SMEM);
    cudaFuncSetAttribute(gemm_f16<float>,  cudaFuncAttributeMaxDynamicSharedMemorySize, GEMM_SMEM);

    // 1. LN + temporal transpose -> fp16
    ln_transpose_kernel<<<TOKENS, 256>>>(x, gamma, beta);

    // 1b. weight conversion
    w2h_kernel<<<(QKV_N * 1024 / 4 + 255) / 256, 256>>>(w_qkv, wqh, QKV_N * 1024);
    w2h_kernel<<<(HIDDEN * 1024 / 4 + 255) / 256, 256>>>(w_out, woh, HIDDEN * 1024);

    // 2. QKV projection: fp16 GEMM -> fp16
    {
        dim3 grid(QKV_N / 256, TOKENS / 128);
        gemm_f16<__half><<<grid, 256, GEMM_SMEM>>>(xh, wqh, qkv, QKV_N);
    }

    // 3. RoPE + causal attention -> fp16 final order
    attn_kernel<<<NSEQ * NH, 64>>>();

    // 4. Output projection -> d_out fp32
    {
        dim3 grid(HIDDEN / 256, TOKENS / 128);
        gemm_f16<float><<<grid, 256, GEMM_SMEM>>>(ah, woh, out, HIDDEN);
    }
}

// round 9
// speedup vs baseline: 1.1148x; 1.1148x over previous
#include <cuda_runtime.h>
#include <cuda_fp16.h>
#include <cstdint>

// ---------------------------------------------------------------------------
// Problem constants
// ---------------------------------------------------------------------------
#define HIDDEN   1024
#define FRAMES   16
#define SPATIAL  1024
#define BATCH    2
#define NSEQ     (BATCH*SPATIAL)        // 2048
#define TOKENS   (BATCH*FRAMES*SPATIAL) // 32768
#define NH       16
#define HD       64
#define QKV_N    3072

// ---------------------------------------------------------------------------
// Scratch
// ---------------------------------------------------------------------------
__device__ __half g_xh [(size_t)TOKENS * HIDDEN];  // LN'd + transposed, fp16
__device__ __half g_wqh[(size_t)QKV_N  * HIDDEN];  // w_qkv fp16
__device__ __half g_woh[(size_t)HIDDEN * HIDDEN];  // w_out fp16
__device__ __half g_ah [(size_t)TOKENS * HIDDEN];  // attn out fp16, final order
__device__ __half g_qkv[(size_t)TOKENS * QKV_N];   // QKV fp16

// ---------------------------------------------------------------------------
// PTX helpers
// ---------------------------------------------------------------------------
__device__ __forceinline__ uint32_t smem_u32(const void* p) {
    uint32_t a;
    asm("{ .reg .u64 t; cvta.to.shared.u64 t, %1; cvt.u32.u64 %0, t; }" : "=r"(a) : "l"(p));
    return a;
}
__device__ __forceinline__ void cp16(uint32_t dst, const void* src) {
    asm volatile("cp.async.cg.shared.global [%0], [%1], 16;" :: "r"(dst), "l"(src));
}
#define CP_COMMIT() asm volatile("cp.async.commit_group;" ::: "memory")
#define CP_WAIT1()  asm volatile("cp.async.wait_group 1;" ::: "memory")

__device__ __forceinline__ void ldmx4(uint32_t addr, uint32_t* r) {
    asm volatile("ldmatrix.sync.aligned.m8n8.x4.shared.b16 {%0,%1,%2,%3}, [%4];"
        : "=r"(r[0]), "=r"(r[1]), "=r"(r[2]), "=r"(r[3]) : "r"(addr));
}
__device__ __forceinline__ void mma_f16(float* d, const uint32_t* a, const uint32_t* b) {
    asm volatile("mma.sync.aligned.m16n8k16.row.col.f32.f16.f16.f32 "
        "{%0,%1,%2,%3},{%4,%5,%6,%7},{%8,%9},{%0,%1,%2,%3};"
        : "+f"(d[0]), "+f"(d[1]), "+f"(d[2]), "+f"(d[3])
        : "r"(a[0]), "r"(a[1]), "r"(a[2]), "r"(a[3]), "r"(b[0]), "r"(b[1]));
}

// byte offset of 16B chunk (r, ch) in a [rows x 128B] tile, SW128 swizzle
__device__ __forceinline__ uint32_t toff(int r, int ch) {
    return (uint32_t)(r * 128 + ((ch ^ (r & 7)) << 4));
}

// ---------------------------------------------------------------------------
// Kernel 1: LayerNorm + temporal transpose -> fp16
// ---------------------------------------------------------------------------
__global__ __launch_bounds__(256) void ln_transpose_kernel(
    const float* __restrict__ x,
    const float* __restrict__ gamma,
    const float* __restrict__ beta)
{
    const int token = blockIdx.x;
    const int b  = token >> 14;
    const int sg = token & 16383;
    const int t  = sg >> 10;
    const int s  = sg & 1023;

    const int tid = threadIdx.x;
    const float4 v = ((const float4*)(x + (size_t)token * HIDDEN))[tid];

    float sum = v.x + v.y + v.z + v.w;
    float sq  = v.x*v.x + v.y*v.y + v.z*v.z + v.w*v.w;

    #pragma unroll
    for (int o = 16; o > 0; o >>= 1) {
        sum += __shfl_xor_sync(0xffffffffu, sum, o);
        sq  += __shfl_xor_sync(0xffffffffu, sq,  o);
    }
    __shared__ float s_sum[8], s_sq[8];
    __shared__ float s_mu, s_rstd;
    if ((tid & 31) == 0) { s_sum[tid >> 5] = sum; s_sq[tid >> 5] = sq; }
    __syncthreads();
    if (tid == 0) {
        float ts = 0.f, tq = 0.f;
        #pragma unroll
        for (int i = 0; i < 8; ++i) { ts += s_sum[i]; tq += s_sq[i]; }
        const float mu  = ts * (1.0f / HIDDEN);
        const float var = tq * (1.0f / HIDDEN) - mu * mu;
        s_mu = mu;
        s_rstd = rsqrtf(var + 1e-5f);
    }
    __syncthreads();
    const float mu = s_mu, rs = s_rstd;

    const float4 g  = ((const float4*)gamma)[tid];
    const float4 be = ((const float4*)beta)[tid];
    __half h[4];
    h[0] = __float2half_rn((v.x - mu) * rs * g.x + be.x);
    h[1] = __float2half_rn((v.y - mu) * rs * g.y + be.y);
    h[2] = __float2half_rn((v.z - mu) * rs * g.z + be.z);
    h[3] = __float2half_rn((v.w - mu) * rs * g.w + be.w);

    const size_t orow = (size_t)(b * SPATIAL + s) * FRAMES + t;
    *(uint2*)(g_xh + orow * HIDDEN + 4 * tid) = *(uint2*)h;
}

// ---------------------------------------------------------------------------
// fp32 -> fp16 weight convert
// ---------------------------------------------------------------------------
__global__ __launch_bounds__(256) void w2h_kernel(
    const float* __restrict__ w, __half* __restrict__ wh, int total)
{
    const int idx = (blockIdx.x * 256 + threadIdx.x) * 4;
    if (idx >= total) return;
    const float4 v = *(const float4*)(w + idx);
    __half h[4] = { __float2half_rn(v.x), __float2half_rn(v.y),
                    __float2half_rn(v.z), __float2half_rn(v.w) };
    *(uint2*)(wh + idx) = *(uint2*)h;
}

// ---------------------------------------------------------------------------
// fp16 mma.sync GEMM: C[M,N] = A[M,1024] * B[N,1024]^T
// BM=128, BN=256, BK=64; 256 threads (8 warps 2x4, warp tile 64x64);
// 3-stage cp.async ring, one sync per chunk, register-double-buffered frags.
// ---------------------------------------------------------------------------
#define KCH 16                    // 1024 / 64
#define A_STG 16384               // 128*64*2
#define B_STG 32768               // 256*64*2
#define STG   (A_STG + B_STG)     // 49152
#define GEMM_SMEM (3 * STG)       // 147456

template <typename OutT>
__global__ __launch_bounds__(256, 1) void gemm_f16(
    const __half* __restrict__ A,
    const __half* __restrict__ B,
    OutT* __restrict__ C, int N)
{
    extern __shared__ __half smem[];
    const uint32_t base = smem_u32(smem);

    const int tid  = threadIdx.x;
    const int lane = tid & 31;
    const int wid  = tid >> 5;
    const int wm   = wid >> 2;         // 0..1  (64-row slab)
    const int wn   = wid & 3;          // 0..3  (64-col slab)
    const int bm   = blockIdx.y * 128;
    const int bn   = blockIdx.x * 256;

    // staging: 3072 16B chunks/stage, 12 per thread
    const int sr  = tid >> 3;          // 0..31
    const int sch = tid & 7;           // 16B chunk within 128B row
    const char* aS[4]; uint32_t aD[4];
    const char* bS[8]; uint32_t bD[8];
    #pragma unroll
    for (int i = 0; i < 4; ++i) {
        aS[i] = (const char*)(A + (size_t)(bm + sr + 32 * i) * HIDDEN) + sch * 16;
        aD[i] = toff(sr + 32 * i, sch);
    }
    #pragma unroll
    for (int i = 0; i < 8; ++i) {
        bS[i] = (const char*)(B + (size_t)(bn + sr + 32 * i) * HIDDEN) + sch * 16;
        bD[i] = A_STG + toff(sr + 32 * i, sch);
    }

    #define LOAD(c, so_abs)                                              \
    {                                                                    \
        const int koff = (c) * 128;                                      \
        _Pragma("unroll")                                                \
        for (int i = 0; i < 4; ++i) cp16((so_abs) + aD[i], aS[i] + koff);\
        _Pragma("unroll")                                                \
        for (int i = 0; i < 8; ++i) cp16((so_abs) + bD[i], bS[i] + koff);\
    }

    // fragment lane coords
    const int arb = wm * 64 + (lane & 15);
    const int ae  = lane >> 4;
    const int brb = wn * 64 + (lane & 7) + (lane >> 4) * 8;
    const int be  = (lane >> 3) & 1;

    float acc[4][8][4];
    #pragma unroll
    for (int i = 0; i < 4; ++i)
        #pragma unroll
        for (int j = 0; j < 8; ++j)
            #pragma unroll
            for (int e = 0; e < 4; ++e) acc[i][j][e] = 0.f;

    uint32_t aq[2][16], bq[2][16];

    #define LDFRAG(buf, so, kk)                                              \
    {                                                                        \
        _Pragma("unroll")                                                    \
        for (int mi = 0; mi < 4; ++mi)                                       \
            ldmx4((so) + toff(arb + mi * 16, (kk) * 2 + ae), &aq[buf][mi*4]);\
        _Pragma("unroll")                                                    \
        for (int p = 0; p < 4; ++p)                                          \
            ldmx4((so) + A_STG + toff(brb + p * 16, (kk) * 2 + be), &bq[buf][p*4]); \
    }

    #define MMAALL(buf)                                                      \
    {                                                                        \
        _Pragma("unroll")                                                    \
        for (int mi = 0; mi < 4; ++mi)                                       \
            _Pragma("unroll")                                                \
            for (int p = 0; p < 4; ++p) {                                    \
                mma_f16(acc[mi][2*p],   &aq[buf][mi*4], &bq[buf][p*4]);      \
                mma_f16(acc[mi][2*p+1], &aq[buf][mi*4], &bq[buf][p*4+2]);    \
            }                                                                \
    }

    // prologue: chunks 0 -> slot0, 1 -> slot1
    LOAD(0, base);       CP_COMMIT();
    LOAD(1, base + STG); CP_COMMIT();

    uint32_t so_rd = base;
    uint32_t so_ld = base + 2 * STG;

    #pragma unroll 1
    for (int c = 0; c < KCH; ++c) {
        CP_WAIT1();
        __syncthreads();

        if (c + 2 < KCH) { LOAD(c + 2, so_ld); }
        CP_COMMIT();
        so_ld += STG; if (so_ld > base + 2 * STG) so_ld = base;

        LDFRAG(0, so_rd, 0);
        LDFRAG(1, so_rd, 1);
        MMAALL(0);
        LDFRAG(0, so_rd, 2);
        MMAALL(1);
        LDFRAG(1, so_rd, 3);
        MMAALL(0);
        MMAALL(1);

        so_rd += STG; if (so_rd > base + 2 * STG) so_rd = base;
    }
    #undef LOAD
    #undef LDFRAG
    #undef MMAALL

    // epilogue
    #pragma unroll
    for (int mi = 0; mi < 4; ++mi) {
        const int row = bm + wm * 64 + mi * 16 + (lane >> 2);
        #pragma unroll
        for (int nj = 0; nj < 8; ++nj) {
            const int col = bn + wn * 64 + nj * 8 + (lane & 3) * 2;
            if (sizeof(OutT) == 4) {
                float* Cf = (float*)C;
                *(float2*)(Cf + (size_t)row * N + col)       = make_float2(acc[mi][nj][0], acc[mi][nj][1]);
                *(float2*)(Cf + (size_t)(row + 8) * N + col) = make_float2(acc[mi][nj][2], acc[mi][nj][3]);
            } else {
                __half* Ch = (__half*)C;
                *(__half2*)(Ch + (size_t)row * N + col)       = __float22half2_rn(make_float2(acc[mi][nj][0], acc[mi][nj][1]));
                *(__half2*)(Ch + (size_t)(row + 8) * N + col) = __float22half2_rn(make_float2(acc[mi][nj][2], acc[mi][nj][3]));
            }
        }
    }
}

// ---------------------------------------------------------------------------
// Kernel 3: RoPE + causal attention (fp16 qkv in, fp16 out, final order)
// ---------------------------------------------------------------------------
__global__ __launch_bounds__(64) void attn_kernel()
{
    const int nb = blockIdx.x;
    const int n  = nb >> 4;
    const int hh = nb & 15;
    const int tid = threadIdx.x;

    __shared__ float qs[FRAMES][HD + 1];
    __shared__ float ks[FRAMES][HD + 1];
    __shared__ float vs[FRAMES][HD + 1];
    __shared__ float P [FRAMES][FRAMES + 1];

    const __half* bptr = g_qkv + (size_t)n * FRAMES * QKV_N + hh * HD;

    for (int idx = tid; idx < FRAMES * 32; idx += 64) {
        const int t  = idx >> 5;
        const int dp = idx & 31;
        const __half* row = bptr + (size_t)t * QKV_N + 2 * dp;
        const float2 q = __half22float2(*(const __half2*)(row));
        const float2 k = __half22float2(*(const __half2*)(row + HIDDEN));
        const float2 v = __half22float2(*(const __half2*)(row + 2 * HIDDEN));
        qs[t][2*dp] = q.x; qs[t][2*dp+1] = q.y;
        ks[t][2*dp] = k.x; ks[t][2*dp+1] = k.y;
        vs[t][2*dp] = v.x; vs[t][2*dp+1] = v.y;
    }
    __syncthreads();

    for (int idx = tid; idx < FRAMES * 32; idx += 64) {
        const int t = idx >> 5;
        const int d = idx & 31;
        const float inv = __expf(-(float)d * 0.28782313662425576f);
        float sn, cs;
        __sincosf((float)t * inv, &sn, &cs);
        const float q1 = qs[t][d], q2 = qs[t][d + 32];
        qs[t][d]      = q1 * cs - q2 * sn;
        qs[t][d + 32] = q2 * cs + q1 * sn;
        const float k1 = ks[t][d], k2 = ks[t][d + 32];
        ks[t][d]      = k1 * cs - k2 * sn;
        ks[t][d + 32] = k2 * cs + k1 * sn;
    }
    __syncthreads();

    for (int idx = tid; idx < FRAMES * FRAMES; idx += 64) {
        const int i = idx >> 4;
        const int j = idx & 15;
        float v = -INFINITY;
        if (j <= i) {
            float acc = 0.f;
            #pragma unroll
            for (int d = 0; d < HD; ++d) acc += qs[i][d] * ks[j][d];
            v = acc * 0.125f;
        }
        P[i][j] = v;
    }
    __syncthreads();

    if (tid < FRAMES) {
        const int i = tid;
        float m = -INFINITY;
        for (int j = 0; j <= i; ++j) m = fmaxf(m, P[i][j]);
        float sum = 0.f;
        for (int j = 0; j <= i; ++j) { const float e = expf(P[i][j] - m); P[i][j] = e; sum += e; }
        const float r = 1.f / sum;
        for (int j = 0; j <= i; ++j) P[i][j] *= r;
        for (int j = i + 1; j < FRAMES; ++j) P[i][j] = 0.f;
    }
    __syncthreads();

    const int d = tid;
    const int b = n >> 10;
    const int s = n & 1023;
    #pragma unroll
    for (int i = 0; i < FRAMES; ++i) {
        float acc = 0.f;
        #pragma unroll
        for (int j = 0; j < FRAMES; ++j) acc += P[i][j] * vs[j][d];
        g_ah[(size_t)(b * 16384 + i * 1024 + s) * HIDDEN + hh * HD + d] = __float2half_rn(acc);
    }
}

// ---------------------------------------------------------------------------
// Launch
// ---------------------------------------------------------------------------
extern "C" void kernel_launch(void* const* d_in, const int* in_sizes, int n_in,
                              void* d_out, int out_size)
{
    const float* x      = (const float*)d_in[0];
    const float* w_qkv  = (const float*)d_in[1];
    const float* w_out  = (const float*)d_in[2];
    const float* gamma  = (const float*)d_in[3];
    const float* beta   = (const float*)d_in[4];
    float* out = (float*)d_out;

    __half *xh, *wqh, *woh, *ah, *qkv;
    cudaGetSymbolAddress((void**)&xh,  g_xh);
    cudaGetSymbolAddress((void**)&wqh, g_wqh);
    cudaGetSymbolAddress((void**)&woh, g_woh);
    cudaGetSymbolAddress((void**)&ah,  g_ah);
    cudaGetSymbolAddress((void**)&qkv, g_qkv);

    cudaFuncSetAttribute(gemm_f16<__half>, cudaFuncAttributeMaxDynamicSharedMemorySize, GEMM_SMEM);
    cudaFuncSetAttribute(gemm_f16<float>,  cudaFuncAttributeMaxDynamicSharedMemorySize, GEMM_SMEM);

    // 1. LN + temporal transpose -> fp16
    ln_transpose_kernel<<<TOKENS, 256>>>(x, gamma, beta);

    // 1b. weight conversion
    w2h_kernel<<<(QKV_N * 1024 / 4 + 255) / 256, 256>>>(w_qkv, wqh, QKV_N * 1024);
    w2h_kernel<<<(HIDDEN * 1024 / 4 + 255) / 256, 256>>>(w_out, woh, HIDDEN * 1024);

    // 2. QKV projection: fp16 GEMM -> fp16
    {
        dim3 grid(QKV_N / 256, TOKENS / 128);
        gemm_f16<__half><<<grid, 256, GEMM_SMEM>>>(xh, wqh, qkv, QKV_N);
    }

    // 3. RoPE + causal attention -> fp16 final order
    attn_kernel<<<NSEQ * NH, 64>>>();

    // 4. Output projection -> d_out fp32
    {
        dim3 grid(HIDDEN / 256, TOKENS / 128);
        gemm_f16<float><<<grid, 256, GEMM_SMEM>>>(ah, woh, out, HIDDEN);
    }
}

// round 10
// speedup vs baseline: 1.1364x; 1.0194x over previous
#include <cuda_runtime.h>
#include <cuda_fp16.h>
#include <cstdint>

// ---------------------------------------------------------------------------
// Problem constants
// ---------------------------------------------------------------------------
#define HIDDEN   1024
#define FRAMES   16
#define SPATIAL  1024
#define BATCH    2
#define NSEQ     (BATCH*SPATIAL)        // 2048
#define TOKENS   (BATCH*FRAMES*SPATIAL) // 32768
#define NH       16
#define HD       64
#define QKV_N    3072

// ---------------------------------------------------------------------------
// Scratch
// ---------------------------------------------------------------------------
__device__ __half g_xh [(size_t)TOKENS * HIDDEN];  // LN'd + transposed, fp16
__device__ __half g_wqh[(size_t)QKV_N  * HIDDEN];  // w_qkv fp16
__device__ __half g_woh[(size_t)HIDDEN * HIDDEN];  // w_out fp16
__device__ __half g_ah [(size_t)TOKENS * HIDDEN];  // attn out fp16, final order
__device__ __half g_qkv[(size_t)TOKENS * QKV_N];   // QKV fp16

// ---------------------------------------------------------------------------
// PTX helpers
// ---------------------------------------------------------------------------
__device__ __forceinline__ uint32_t smem_u32(const void* p) {
    uint32_t a;
    asm("{ .reg .u64 t; cvta.to.shared.u64 t, %1; cvt.u32.u64 %0, t; }" : "=r"(a) : "l"(p));
    return a;
}
__device__ __forceinline__ void cp16(uint32_t dst, const void* src) {
    asm volatile("cp.async.cg.shared.global [%0], [%1], 16;" :: "r"(dst), "l"(src));
}
#define CP_COMMIT() asm volatile("cp.async.commit_group;" ::: "memory")
#define CP_WAIT0()  asm volatile("cp.async.wait_group 0;" ::: "memory")

__device__ __forceinline__ void ldmx4(uint32_t addr, uint32_t* r) {
    asm volatile("ldmatrix.sync.aligned.m8n8.x4.shared.b16 {%0,%1,%2,%3}, [%4];"
        : "=r"(r[0]), "=r"(r[1]), "=r"(r[2]), "=r"(r[3]) : "r"(addr));
}
// NOTE: non-volatile on purpose — pure register op; lets the compiler
// interleave LDSM issue into the HMMA dispatch stream.
__device__ __forceinline__ void mma_f16(float* d, const uint32_t* a, const uint32_t* b) {
    asm("mma.sync.aligned.m16n8k16.row.col.f32.f16.f16.f32 "
        "{%0,%1,%2,%3},{%4,%5,%6,%7},{%8,%9},{%0,%1,%2,%3};"
        : "+f"(d[0]), "+f"(d[1]), "+f"(d[2]), "+f"(d[3])
        : "r"(a[0]), "r"(a[1]), "r"(a[2]), "r"(a[3]), "r"(b[0]), "r"(b[1]));
}

// byte offset of 16B chunk (r, ch) in a [rows x 128B] tile, SW128 swizzle
__device__ __forceinline__ uint32_t toff(int r, int ch) {
    return (uint32_t)(r * 128 + ((ch ^ (r & 7)) << 4));
}

// ---------------------------------------------------------------------------
// Kernel 1: LayerNorm + temporal transpose -> fp16
// ---------------------------------------------------------------------------
__global__ __launch_bounds__(256) void ln_transpose_kernel(
    const float* __restrict__ x,
    const float* __restrict__ gamma,
    const float* __restrict__ beta)
{
    const int token = blockIdx.x;
    const int b  = token >> 14;
    const int sg = token & 16383;
    const int t  = sg >> 10;
    const int s  = sg & 1023;

    const int tid = threadIdx.x;
    const float4 v = ((const float4*)(x + (size_t)token * HIDDEN))[tid];

    float sum = v.x + v.y + v.z + v.w;
    float sq  = v.x*v.x + v.y*v.y + v.z*v.z + v.w*v.w;

    #pragma unroll
    for (int o = 16; o > 0; o >>= 1) {
        sum += __shfl_xor_sync(0xffffffffu, sum, o);
        sq  += __shfl_xor_sync(0xffffffffu, sq,  o);
    }
    __shared__ float s_sum[8], s_sq[8];
    __shared__ float s_mu, s_rstd;
    if ((tid & 31) == 0) { s_sum[tid >> 5] = sum; s_sq[tid >> 5] = sq; }
    __syncthreads();
    if (tid == 0) {
        float ts = 0.f, tq = 0.f;
        #pragma unroll
        for (int i = 0; i < 8; ++i) { ts += s_sum[i]; tq += s_sq[i]; }
        const float mu  = ts * (1.0f / HIDDEN);
        const float var = tq * (1.0f / HIDDEN) - mu * mu;
        s_mu = mu;
        s_rstd = rsqrtf(var + 1e-5f);
    }
    __syncthreads();
    const float mu = s_mu, rs = s_rstd;

    const float4 g  = ((const float4*)gamma)[tid];
    const float4 be = ((const float4*)beta)[tid];
    __half h[4];
    h[0] = __float2half_rn((v.x - mu) * rs * g.x + be.x);
    h[1] = __float2half_rn((v.y - mu) * rs * g.y + be.y);
    h[2] = __float2half_rn((v.z - mu) * rs * g.z + be.z);
    h[3] = __float2half_rn((v.w - mu) * rs * g.w + be.w);

    const size_t orow = (size_t)(b * SPATIAL + s) * FRAMES + t;
    *(uint2*)(g_xh + orow * HIDDEN + 4 * tid) = *(uint2*)h;
}

// ---------------------------------------------------------------------------
// fp32 -> fp16 weight convert
// ---------------------------------------------------------------------------
__global__ __launch_bounds__(256) void w2h_kernel(
    const float* __restrict__ w, __half* __restrict__ wh, int total)
{
    const int idx = (blockIdx.x * 256 + threadIdx.x) * 4;
    if (idx >= total) return;
    const float4 v = *(const float4*)(w + idx);
    __half h[4] = { __float2half_rn(v.x), __float2half_rn(v.y),
                    __float2half_rn(v.z), __float2half_rn(v.w) };
    *(uint2*)(wh + idx) = *(uint2*)h;
}

// ---------------------------------------------------------------------------
// fp16 mma.sync GEMM: C[M,N] = A[M,1024] * B[N,1024]^T
// BM=128, BN=256, BK=128 (two 64-K sub-tiles per stage); 256 threads
// (8 warps 2x4, warp tile 64x64); 2-stage cp.async ring, one sync per chunk,
// register-double-buffered fragments.
// ---------------------------------------------------------------------------
#define KCH 8                     // 1024 / 128
#define A_SUB 16384               // 128 rows * 128B (64 halfs)
#define B_SUB 32768               // 256 rows * 128B
#define STG   (2*A_SUB + 2*B_SUB) // 98304
#define GEMM_SMEM (2 * STG)       // 196608

template <typename OutT>
__global__ __launch_bounds__(256, 1) void gemm_f16(
    const __half* __restrict__ A,
    const __half* __restrict__ B,
    OutT* __restrict__ C, int N)
{
    extern __shared__ __half smem[];
    const uint32_t base = smem_u32(smem);

    const int tid  = threadIdx.x;
    const int lane = tid & 31;
    const int wid  = tid >> 5;
    const int wm   = wid >> 2;         // 0..1  (64-row slab)
    const int wn   = wid & 3;          // 0..3  (64-col slab)
    const int bm   = blockIdx.y * 128;
    const int bn   = blockIdx.x * 256;

    // staging: per stage 2 sub-tiles; per thread 24 cp16
    const int sr  = tid >> 3;          // 0..31
    const int sch = tid & 7;           // 16B chunk within 128B sub-row
    const char* aS[4]; uint32_t aD[4];
    const char* bS[8]; uint32_t bD[8];
    #pragma unroll
    for (int i = 0; i < 4; ++i) {
        aS[i] = (const char*)(A + (size_t)(bm + sr + 32 * i) * HIDDEN) + sch * 16;
        aD[i] = toff(sr + 32 * i, sch);
    }
    #pragma unroll
    for (int i = 0; i < 8; ++i) {
        bS[i] = (const char*)(B + (size_t)(bn + sr + 32 * i) * HIDDEN) + sch * 16;
        bD[i] = toff(sr + 32 * i, sch);
    }

    // LOAD chunk c (256B of K per row) into stage at absolute smem addr so_abs
    #define LOAD(c, so_abs)                                                     \
    {                                                                           \
        _Pragma("unroll")                                                       \
        for (int s = 0; s < 2; ++s) {                                           \
            const int koff = (c) * 256 + s * 128;                               \
            _Pragma("unroll")                                                   \
            for (int i = 0; i < 4; ++i)                                         \
                cp16((so_abs) + s * A_SUB + aD[i], aS[i] + koff);               \
            _Pragma("unroll")                                                   \
            for (int i = 0; i < 8; ++i)                                         \
                cp16((so_abs) + 2 * A_SUB + s * B_SUB + bD[i], bS[i] + koff);   \
        }                                                                       \
    }

    // fragment lane coords
    const int arb = wm * 64 + (lane & 15);
    const int ae  = lane >> 4;
    const int brb = wn * 64 + (lane & 7) + (lane >> 4) * 8;
    const int be  = (lane >> 3) & 1;

    float acc[4][8][4];
    #pragma unroll
    for (int i = 0; i < 4; ++i)
        #pragma unroll
        for (int j = 0; j < 8; ++j)
            #pragma unroll
            for (int e = 0; e < 4; ++e) acc[i][j][e] = 0.f;

    uint32_t aq[2][16], bq[2][16];

    // kk in 0..7 selects sub-tile kk>>2, local k16-group kk&3
    #define LDFRAG(buf, so, kk)                                                  \
    {                                                                            \
        const uint32_t asub = (so) + ((kk) >> 2) * A_SUB;                        \
        const uint32_t bsub = (so) + 2 * A_SUB + ((kk) >> 2) * B_SUB;            \
        const int kkl = (kk) & 3;                                                \
        _Pragma("unroll")                                                        \
        for (int mi = 0; mi < 4; ++mi)                                           \
            ldmx4(asub + toff(arb + mi * 16, kkl * 2 + ae), &aq[buf][mi*4]);     \
        _Pragma("unroll")                                                        \
        for (int p = 0; p < 4; ++p)                                              \
            ldmx4(bsub + toff(brb + p * 16, kkl * 2 + be), &bq[buf][p*4]);       \
    }

    #define MMAALL(buf)                                                          \
    {                                                                            \
        _Pragma("unroll")                                                        \
        for (int mi = 0; mi < 4; ++mi)                                           \
            _Pragma("unroll")                                                    \
            for (int p = 0; p < 4; ++p) {                                        \
                mma_f16(acc[mi][2*p],   &aq[buf][mi*4], &bq[buf][p*4]);          \
                mma_f16(acc[mi][2*p+1], &aq[buf][mi*4], &bq[buf][p*4+2]);        \
            }                                                                    \
    }

    // prologue: chunk 0 -> slot 0
    LOAD(0, base);
    CP_COMMIT();

    uint32_t so_rd = base;
    uint32_t so_ld = base + STG;

    #pragma unroll 1
    for (int c = 0; c < KCH; ++c) {
        CP_WAIT0();          // chunk c data arrived (this thread's group)
        __syncthreads();     // visibility + all warps done reading slot so_ld

        if (c + 1 < KCH) { LOAD(c + 1, so_ld); }
        CP_COMMIT();

        LDFRAG(0, so_rd, 0);
        LDFRAG(1, so_rd, 1);
        MMAALL(0); LDFRAG(0, so_rd, 2);
        MMAALL(1); LDFRAG(1, so_rd, 3);
        MMAALL(0); LDFRAG(0, so_rd, 4);
        MMAALL(1); LDFRAG(1, so_rd, 5);
        MMAALL(0); LDFRAG(0, so_rd, 6);
        MMAALL(1); LDFRAG(1, so_rd, 7);
        MMAALL(0);
        MMAALL(1);

        // swap slots
        const uint32_t tmp = so_rd; so_rd = so_ld; so_ld = tmp;
    }
    #undef LOAD
    #undef LDFRAG
    #undef MMAALL

    // epilogue
    #pragma unroll
    for (int mi = 0; mi < 4; ++mi) {
        const int row = bm + wm * 64 + mi * 16 + (lane >> 2);
        #pragma unroll
        for (int nj = 0; nj < 8; ++nj) {
            const int col = bn + wn * 64 + nj * 8 + (lane & 3) * 2;
            if (sizeof(OutT) == 4) {
                float* Cf = (float*)C;
                *(float2*)(Cf + (size_t)row * N + col)       = make_float2(acc[mi][nj][0], acc[mi][nj][1]);
                *(float2*)(Cf + (size_t)(row + 8) * N + col) = make_float2(acc[mi][nj][2], acc[mi][nj][3]);
            } else {
                __half* Ch = (__half*)C;
                *(__half2*)(Ch + (size_t)row * N + col)       = __float22half2_rn(make_float2(acc[mi][nj][0], acc[mi][nj][1]));
                *(__half2*)(Ch + (size_t)(row + 8) * N + col) = __float22half2_rn(make_float2(acc[mi][nj][2], acc[mi][nj][3]));
            }
        }
    }
}

// ---------------------------------------------------------------------------
// Kernel 3: RoPE + causal attention (fp16 qkv in, fp16 out, final order)
// ---------------------------------------------------------------------------
__global__ __launch_bounds__(64) void attn_kernel()
{
    const int nb = blockIdx.x;
    const int n  = nb >> 4;
    const int hh = nb & 15;
    const int tid = threadIdx.x;

    __shared__ float qs[FRAMES][HD + 1];
    __shared__ float ks[FRAMES][HD + 1];
    __shared__ float vs[FRAMES][HD + 1];
    __shared__ float P [FRAMES][FRAMES + 1];

    const __half* bptr = g_qkv + (size_t)n * FRAMES * QKV_N + hh * HD;

    for (int idx = tid; idx < FRAMES * 32; idx += 64) {
        const int t  = idx >> 5;
        const int dp = idx & 31;
        const __half* row = bptr + (size_t)t * QKV_N + 2 * dp;
        const float2 q = __half22float2(*(const __half2*)(row));
        const float2 k = __half22float2(*(const __half2*)(row + HIDDEN));
        const float2 v = __half22float2(*(const __half2*)(row + 2 * HIDDEN));
        qs[t][2*dp] = q.x; qs[t][2*dp+1] = q.y;
        ks[t][2*dp] = k.x; ks[t][2*dp+1] = k.y;
        vs[t][2*dp] = v.x; vs[t][2*dp+1] = v.y;
    }
    __syncthreads();

    for (int idx = tid; idx < FRAMES * 32; idx += 64) {
        const int t = idx >> 5;
        const int d = idx & 31;
        const float inv = __expf(-(float)d * 0.28782313662425576f);
        float sn, cs;
        __sincosf((float)t * inv, &sn, &cs);
        const float q1 = qs[t][d], q2 = qs[t][d + 32];
        qs[t][d]      = q1 * cs - q2 * sn;
        qs[t][d + 32] = q2 * cs + q1 * sn;
        const float k1 = ks[t][d], k2 = ks[t][d + 32];
        ks[t][d]      = k1 * cs - k2 * sn;
        ks[t][d + 32] = k2 * cs + k1 * sn;
    }
    __syncthreads();

    for (int idx = tid; idx < FRAMES * FRAMES; idx += 64) {
        const int i = idx >> 4;
        const int j = idx & 15;
        float v = -INFINITY;
        if (j <= i) {
            float acc = 0.f;
            #pragma unroll
            for (int d = 0; d < HD; ++d) acc += qs[i][d] * ks[j][d];
            v = acc * 0.125f;
        }
        P[i][j] = v;
    }
    __syncthreads();

    if (tid < FRAMES) {
        const int i = tid;
        float m = -INFINITY;
        for (int j = 0; j <= i; ++j) m = fmaxf(m, P[i][j]);
        float sum = 0.f;
        for (int j = 0; j <= i; ++j) { const float e = __expf(P[i][j] - m); P[i][j] = e; sum += e; }
        const float r = 1.f / sum;
        for (int j = 0; j <= i; ++j) P[i][j] *= r;
        for (int j = i + 1; j < FRAMES; ++j) P[i][j] = 0.f;
    }
    __syncthreads();

    const int d = tid;
    const int b = n >> 10;
    const int s = n & 1023;
    #pragma unroll
    for (int i = 0; i < FRAMES; ++i) {
        float acc = 0.f;
        #pragma unroll
        for (int j = 0; j < FRAMES; ++j) acc += P[i][j] * vs[j][d];
        g_ah[(size_t)(b * 16384 + i * 1024 + s) * HIDDEN + hh * HD + d] = __float2half_rn(acc);
    }
}

// ---------------------------------------------------------------------------
// Launch
// ---------------------------------------------------------------------------
extern "C" void kernel_launch(void* const* d_in, const int* in_sizes, int n_in,
                              void* d_out, int out_size)
{
    const float* x      = (const float*)d_in[0];
    const float* w_qkv  = (const float*)d_in[1];
    const float* w_out  = (const float*)d_in[2];
    const float* gamma  = (const float*)d_in[3];
    const float* beta   = (const float*)d_in[4];
    float* out = (float*)d_out;

    __half *xh, *wqh, *woh, *ah, *qkv;
    cudaGetSymbolAddress((void**)&xh,  g_xh);
    cudaGetSymbolAddress((void**)&wqh, g_wqh);
    cudaGetSymbolAddress((void**)&woh, g_woh);
    cudaGetSymbolAddress((void**)&ah,  g_ah);
    cudaGetSymbolAddress((void**)&qkv, g_qkv);

    cudaFuncSetAttribute(gemm_f16<__half>, cudaFuncAttributeMaxDynamicSharedMemorySize, GEMM_SMEM);
    cudaFuncSetAttribute(gemm_f16<float>,  cudaFuncAttributeMaxDynamicSharedMemorySize, GEMM_SMEM);

    // 1. LN + temporal transpose -> fp16
    ln_transpose_kernel<<<TOKENS, 256>>>(x, gamma, beta);

    // 1b. weight conversion
    w2h_kernel<<<(QKV_N * 1024 / 4 + 255) / 256, 256>>>(w_qkv, wqh, QKV_N * 1024);
    w2h_kernel<<<(HIDDEN * 1024 / 4 + 255) / 256, 256>>>(w_out, woh, HIDDEN * 1024);

    // 2. QKV projection: fp16 GEMM -> fp16
    {
        dim3 grid(QKV_N / 256, TOKENS / 128);
        gemm_f16<__half><<<grid, 256, GEMM_SMEM>>>(xh, wqh, qkv, QKV_N);
    }

    // 3. RoPE + causal attention -> fp16 final order
    attn_kernel<<<NSEQ * NH, 64>>>();

    // 4. Output projection -> d_out fp32
    {
        dim3 grid(HIDDEN / 256, TOKENS / 128);
        gemm_f16<float><<<grid, 256, GEMM_SMEM>>>(ah, woh, out, HIDDEN);
    }
}

// round 11
// speedup vs baseline: 1.2531x; 1.1027x over previous
#include <cuda_runtime.h>
#include <cuda_fp16.h>
#include <cstdint>

// ---------------------------------------------------------------------------
// Problem constants
// ---------------------------------------------------------------------------
#define HIDDEN   1024
#define FRAMES   16
#define SPATIAL  1024
#define BATCH    2
#define NSEQ     (BATCH*SPATIAL)        // 2048
#define TOKENS   (BATCH*FRAMES*SPATIAL) // 32768
#define NH       16
#define HD       64
#define QKV_N    3072

// ---------------------------------------------------------------------------
// Scratch
// ---------------------------------------------------------------------------
__device__ __half g_xh [(size_t)TOKENS * HIDDEN];  // LN'd + transposed, fp16
__device__ __half g_wqh[(size_t)QKV_N  * HIDDEN];  // w_qkv fp16
__device__ __half g_woh[(size_t)HIDDEN * HIDDEN];  // w_out fp16
__device__ __half g_ah [(size_t)TOKENS * HIDDEN];  // attn out fp16, final order
__device__ __half g_qkv[(size_t)TOKENS * QKV_N];   // QKV fp16

// ---------------------------------------------------------------------------
// PTX helpers
// ---------------------------------------------------------------------------
__device__ __forceinline__ uint32_t smem_u32(const void* p) {
    uint32_t a;
    asm("{ .reg .u64 t; cvta.to.shared.u64 t, %1; cvt.u32.u64 %0, t; }" : "=r"(a) : "l"(p));
    return a;
}
__device__ __forceinline__ void cp16(uint32_t dst, const void* src) {
    asm volatile("cp.async.cg.shared.global [%0], [%1], 16;" :: "r"(dst), "l"(src));
}
#define CP_COMMIT() asm volatile("cp.async.commit_group;" ::: "memory")
#define CP_WAIT0()  asm volatile("cp.async.wait_group 0;" ::: "memory")

__device__ __forceinline__ void ldmx4(uint32_t addr, uint32_t* r) {
    asm volatile("ldmatrix.sync.aligned.m8n8.x4.shared.b16 {%0,%1,%2,%3}, [%4];"
        : "=r"(r[0]), "=r"(r[1]), "=r"(r[2]), "=r"(r[3]) : "r"(addr));
}
// variant with memory clobber (attention: smem written by plain stores)
__device__ __forceinline__ void ldmx4m(uint32_t addr, uint32_t* r) {
    asm volatile("ldmatrix.sync.aligned.m8n8.x4.shared.b16 {%0,%1,%2,%3}, [%4];"
        : "=r"(r[0]), "=r"(r[1]), "=r"(r[2]), "=r"(r[3]) : "r"(addr) : "memory");
}
// non-volatile: pure register op, lets compiler interleave with LDSM
__device__ __forceinline__ void mma_f16(float* d, const uint32_t* a, const uint32_t* b) {
    asm("mma.sync.aligned.m16n8k16.row.col.f32.f16.f16.f32 "
        "{%0,%1,%2,%3},{%4,%5,%6,%7},{%8,%9},{%0,%1,%2,%3};"
        : "+f"(d[0]), "+f"(d[1]), "+f"(d[2]), "+f"(d[3])
        : "r"(a[0]), "r"(a[1]), "r"(a[2]), "r"(a[3]), "r"(b[0]), "r"(b[1]));
}

// byte offset of 16B chunk (r, ch) in a [rows x 128B] tile, SW128 swizzle
__device__ __forceinline__ uint32_t toff(int r, int ch) {
    return (uint32_t)(r * 128 + ((ch ^ (r & 7)) << 4));
}
// element pointer into a swizzled [16 x 64 half] tile
__device__ __forceinline__ __half* sptr(__half* base, int t, int d) {
    return (__half*)((char*)base + t * 128 + (((d >> 3) ^ (t & 7)) << 4) + (d & 7) * 2);
}

// ---------------------------------------------------------------------------
// Kernel 1: LayerNorm + temporal transpose -> fp16
// ---------------------------------------------------------------------------
__global__ __launch_bounds__(256) void ln_transpose_kernel(
    const float* __restrict__ x,
    const float* __restrict__ gamma,
    const float* __restrict__ beta)
{
    const int token = blockIdx.x;
    const int b  = token >> 14;
    const int sg = token & 16383;
    const int t  = sg >> 10;
    const int s  = sg & 1023;

    const int tid = threadIdx.x;
    const float4 v = ((const float4*)(x + (size_t)token * HIDDEN))[tid];

    float sum = v.x + v.y + v.z + v.w;
    float sq  = v.x*v.x + v.y*v.y + v.z*v.z + v.w*v.w;

    #pragma unroll
    for (int o = 16; o > 0; o >>= 1) {
        sum += __shfl_xor_sync(0xffffffffu, sum, o);
        sq  += __shfl_xor_sync(0xffffffffu, sq,  o);
    }
    __shared__ float s_sum[8], s_sq[8];
    __shared__ float s_mu, s_rstd;
    if ((tid & 31) == 0) { s_sum[tid >> 5] = sum; s_sq[tid >> 5] = sq; }
    __syncthreads();
    if (tid == 0) {
        float ts = 0.f, tq = 0.f;
        #pragma unroll
        for (int i = 0; i < 8; ++i) { ts += s_sum[i]; tq += s_sq[i]; }
        const float mu  = ts * (1.0f / HIDDEN);
        const float var = tq * (1.0f / HIDDEN) - mu * mu;
        s_mu = mu;
        s_rstd = rsqrtf(var + 1e-5f);
    }
    __syncthreads();
    const float mu = s_mu, rs = s_rstd;

    const float4 g  = ((const float4*)gamma)[tid];
    const float4 be = ((const float4*)beta)[tid];
    __half h[4];
    h[0] = __float2half_rn((v.x - mu) * rs * g.x + be.x);
    h[1] = __float2half_rn((v.y - mu) * rs * g.y + be.y);
    h[2] = __float2half_rn((v.z - mu) * rs * g.z + be.z);
    h[3] = __float2half_rn((v.w - mu) * rs * g.w + be.w);

    const size_t orow = (size_t)(b * SPATIAL + s) * FRAMES + t;
    *(uint2*)(g_xh + orow * HIDDEN + 4 * tid) = *(uint2*)h;
}

// ---------------------------------------------------------------------------
// fp32 -> fp16 weight convert
// ---------------------------------------------------------------------------
__global__ __launch_bounds__(256) void w2h_kernel(
    const float* __restrict__ w, __half* __restrict__ wh, int total)
{
    const int idx = (blockIdx.x * 256 + threadIdx.x) * 4;
    if (idx >= total) return;
    const float4 v = *(const float4*)(w + idx);
    __half h[4] = { __float2half_rn(v.x), __float2half_rn(v.y),
                    __float2half_rn(v.z), __float2half_rn(v.w) };
    *(uint2*)(wh + idx) = *(uint2*)h;
}

// ---------------------------------------------------------------------------
// fp16 mma.sync GEMM (unchanged from R10): BM=128, BN=256, BK=128,
// 256 threads, warp tile 64x64, 2-stage cp.async ring.
// ---------------------------------------------------------------------------
#define KCH 8                     // 1024 / 128
#define A_SUB 16384               // 128 rows * 128B
#define B_SUB 32768               // 256 rows * 128B
#define STG   (2*A_SUB + 2*B_SUB) // 98304
#define GEMM_SMEM (2 * STG)       // 196608

template <typename OutT>
__global__ __launch_bounds__(256, 1) void gemm_f16(
    const __half* __restrict__ A,
    const __half* __restrict__ B,
    OutT* __restrict__ C, int N)
{
    extern __shared__ __half smem[];
    const uint32_t base = smem_u32(smem);

    const int tid  = threadIdx.x;
    const int lane = tid & 31;
    const int wid  = tid >> 5;
    const int wm   = wid >> 2;
    const int wn   = wid & 3;
    const int bm   = blockIdx.y * 128;
    const int bn   = blockIdx.x * 256;

    const int sr  = tid >> 3;
    const int sch = tid & 7;
    const char* aS[4]; uint32_t aD[4];
    const char* bS[8]; uint32_t bD[8];
    #pragma unroll
    for (int i = 0; i < 4; ++i) {
        aS[i] = (const char*)(A + (size_t)(bm + sr + 32 * i) * HIDDEN) + sch * 16;
        aD[i] = toff(sr + 32 * i, sch);
    }
    #pragma unroll
    for (int i = 0; i < 8; ++i) {
        bS[i] = (const char*)(B + (size_t)(bn + sr + 32 * i) * HIDDEN) + sch * 16;
        bD[i] = toff(sr + 32 * i, sch);
    }

    #define LOAD(c, so_abs)                                                     \
    {                                                                           \
        _Pragma("unroll")                                                       \
        for (int s = 0; s < 2; ++s) {                                           \
            const int koff = (c) * 256 + s * 128;                               \
            _Pragma("unroll")                                                   \
            for (int i = 0; i < 4; ++i)                                         \
                cp16((so_abs) + s * A_SUB + aD[i], aS[i] + koff);               \
            _Pragma("unroll")                                                   \
            for (int i = 0; i < 8; ++i)                                         \
                cp16((so_abs) + 2 * A_SUB + s * B_SUB + bD[i], bS[i] + koff);   \
        }                                                                       \
    }

    const int arb = wm * 64 + (lane & 15);
    const int ae  = lane >> 4;
    const int brb = wn * 64 + (lane & 7) + (lane >> 4) * 8;
    const int be  = (lane >> 3) & 1;

    float acc[4][8][4];
    #pragma unroll
    for (int i = 0; i < 4; ++i)
        #pragma unroll
        for (int j = 0; j < 8; ++j)
            #pragma unroll
            for (int e = 0; e < 4; ++e) acc[i][j][e] = 0.f;

    uint32_t aq[2][16], bq[2][16];

    #define LDFRAG(buf, so, kk)                                                  \
    {                                                                            \
        const uint32_t asub = (so) + ((kk) >> 2) * A_SUB;                        \
        const uint32_t bsub = (so) + 2 * A_SUB + ((kk) >> 2) * B_SUB;            \
        const int kkl = (kk) & 3;                                                \
        _Pragma("unroll")                                                        \
        for (int mi = 0; mi < 4; ++mi)                                           \
            ldmx4(asub + toff(arb + mi * 16, kkl * 2 + ae), &aq[buf][mi*4]);     \
        _Pragma("unroll")                                                        \
        for (int p = 0; p < 4; ++p)                                              \
            ldmx4(bsub + toff(brb + p * 16, kkl * 2 + be), &bq[buf][p*4]);       \
    }

    #define MMAALL(buf)                                                          \
    {                                                                            \
        _Pragma("unroll")                                                        \
        for (int mi = 0; mi < 4; ++mi)                                           \
            _Pragma("unroll")                                                    \
            for (int p = 0; p < 4; ++p) {                                        \
                mma_f16(acc[mi][2*p],   &aq[buf][mi*4], &bq[buf][p*4]);          \
                mma_f16(acc[mi][2*p+1], &aq[buf][mi*4], &bq[buf][p*4+2]);        \
            }                                                                    \
    }

    LOAD(0, base);
    CP_COMMIT();

    uint32_t so_rd = base;
    uint32_t so_ld = base + STG;

    #pragma unroll 1
    for (int c = 0; c < KCH; ++c) {
        CP_WAIT0();
        __syncthreads();

        if (c + 1 < KCH) { LOAD(c + 1, so_ld); }
        CP_COMMIT();

        LDFRAG(0, so_rd, 0);
        LDFRAG(1, so_rd, 1);
        MMAALL(0); LDFRAG(0, so_rd, 2);
        MMAALL(1); LDFRAG(1, so_rd, 3);
        MMAALL(0); LDFRAG(0, so_rd, 4);
        MMAALL(1); LDFRAG(1, so_rd, 5);
        MMAALL(0); LDFRAG(0, so_rd, 6);
        MMAALL(1); LDFRAG(1, so_rd, 7);
        MMAALL(0);
        MMAALL(1);

        const uint32_t tmp = so_rd; so_rd = so_ld; so_ld = tmp;
    }
    #undef LOAD
    #undef LDFRAG
    #undef MMAALL

    #pragma unroll
    for (int mi = 0; mi < 4; ++mi) {
        const int row = bm + wm * 64 + mi * 16 + (lane >> 2);
        #pragma unroll
        for (int nj = 0; nj < 8; ++nj) {
            const int col = bn + wn * 64 + nj * 8 + (lane & 3) * 2;
            if (sizeof(OutT) == 4) {
                float* Cf = (float*)C;
                *(float2*)(Cf + (size_t)row * N + col)       = make_float2(acc[mi][nj][0], acc[mi][nj][1]);
                *(float2*)(Cf + (size_t)(row + 8) * N + col) = make_float2(acc[mi][nj][2], acc[mi][nj][3]);
            } else {
                __half* Ch = (__half*)C;
                *(__half2*)(Ch + (size_t)row * N + col)       = __float22half2_rn(make_float2(acc[mi][nj][0], acc[mi][nj][1]));
                *(__half2*)(Ch + (size_t)(row + 8) * N + col) = __float22half2_rn(make_float2(acc[mi][nj][2], acc[mi][nj][3]));
            }
        }
    }
}

// ---------------------------------------------------------------------------
// Kernel 3: MMA-based RoPE + causal attention. One warp per (n, head).
// 128 threads = 4 warps per block; grid = NSEQ*NH/4 = 8192.
// S = Q*K^T via m16n8k16 (fp16 in, fp32 acc), softmax in c-frag registers,
// P packed to fp16 a-frags in-register, O = P*V^T-mma, stored to g_ah.
// ---------------------------------------------------------------------------
#define VT_PITCH 24   // halfs per V^T row (48B, odd 16B multiple: conflict-free)

__global__ __launch_bounds__(128) void attn_kernel()
{
    const int wib  = threadIdx.x >> 5;
    const int lane = threadIdx.x & 31;
    const int nb = blockIdx.x * 4 + wib;   // 0..32767
    const int n  = nb >> 4;
    const int hh = nb & 15;

    __shared__ __align__(16) __half sQ [4][FRAMES * HD];        // swizzled 128B rows
    __shared__ __align__(16) __half sK [4][FRAMES * HD];
    __shared__ __align__(16) __half sVT[4][HD * VT_PITCH];      // V^T, 48B pitch

    __half* q  = sQ[wib];
    __half* k  = sK[wib];
    __half* vt = sVT[wib];

    const __half* gq = g_qkv + (size_t)n * FRAMES * QKV_N + hh * HD;

    // phase 1: cooperative copy Q,K (swizzled) + V transpose
    #pragma unroll
    for (int i = 0; i < 4; ++i) {
        const int id = lane + 32 * i;      // 0..127
        const int r  = id >> 3;            // frame 0..15
        const int ch = id & 7;             // 16B chunk (8 halfs of d)
        const char* rowp = (const char*)(gq + (size_t)r * QKV_N) + ch * 16;
        *(uint4*)((char*)q + toff(r, ch)) = *(const uint4*)(rowp);
        *(uint4*)((char*)k + toff(r, ch)) = *(const uint4*)(rowp + HIDDEN * 2);
        uint4 vv = *(const uint4*)(rowp + 2 * HIDDEN * 2);
        const __half* vh = (const __half*)&vv;
        #pragma unroll
        for (int e = 0; e < 8; ++e) vt[(ch * 8 + e) * VT_PITCH + r] = vh[e];
    }
    __syncwarp();

    // phase 2: RoPE in smem (Q scaled by 1/sqrt(64)=0.125)
    {
        const int t  = lane >> 1;
        const int pb = (lane & 1) * 16;
        #pragma unroll
        for (int p = 0; p < 16; ++p) {
            const int d = pb + p;          // 0..31
            const float inv = __expf(-(float)d * 0.28782313662425576f);
            float sn, cs;
            __sincosf((float)t * inv, &sn, &cs);
            __half *q1p = sptr(q, t, d), *q2p = sptr(q, t, d + 32);
            const float q1 = __half2float(*q1p), q2 = __half2float(*q2p);
            *q1p = __float2half_rn((q1 * cs - q2 * sn) * 0.125f);
            *q2p = __float2half_rn((q2 * cs + q1 * sn) * 0.125f);
            __half *k1p = sptr(k, t, d), *k2p = sptr(k, t, d + 32);
            const float k1 = __half2float(*k1p), k2 = __half2float(*k2p);
            *k1p = __float2half_rn(k1 * cs - k2 * sn);
            *k2p = __float2half_rn(k2 * cs + k1 * sn);
        }
    }
    __syncwarp();

    // S = Q * K^T  (A-frags from Q, B-frags from K — proven GEMM patterns)
    const uint32_t qb = smem_u32(q), kb = smem_u32(k), vb = smem_u32(vt);
    const int arb = lane & 15;
    const int ae  = lane >> 4;
    const int brb = (lane & 7) + ((lane >> 4) << 3);
    const int be  = (lane >> 3) & 1;

    float s0[4] = {0.f, 0.f, 0.f, 0.f};    // cols 0-7
    float s1[4] = {0.f, 0.f, 0.f, 0.f};    // cols 8-15
    #pragma unroll
    for (int kg = 0; kg < 4; ++kg) {
        uint32_t aq[4], bq[4];
        ldmx4m(qb + toff(arb, kg * 2 + ae), aq);
        ldmx4m(kb + toff(brb, kg * 2 + be), bq);
        mma_f16(s0, aq, bq);
        mma_f16(s1, aq, bq + 2);
    }

    // softmax in c-frag registers
    const int rlo = lane >> 2, rhi = rlo + 8;
    const int c0  = 2 * (lane & 3);
    const int jc[4] = {c0, c0 + 1, c0 + 8, c0 + 9};
    float vlo[4] = {s0[0], s0[1], s1[0], s1[1]};
    float vhi[4] = {s0[2], s0[3], s1[2], s1[3]};

    float mlo = -1e30f, mhi = -1e30f;
    #pragma unroll
    for (int e = 0; e < 4; ++e) {
        if (jc[e] <= rlo) mlo = fmaxf(mlo, vlo[e]);
        if (jc[e] <= rhi) mhi = fmaxf(mhi, vhi[e]);
    }
    mlo = fmaxf(mlo, __shfl_xor_sync(0xffffffffu, mlo, 1));
    mlo = fmaxf(mlo, __shfl_xor_sync(0xffffffffu, mlo, 2));
    mhi = fmaxf(mhi, __shfl_xor_sync(0xffffffffu, mhi, 1));
    mhi = fmaxf(mhi, __shfl_xor_sync(0xffffffffu, mhi, 2));

    float elo[4], ehi[4], slo = 0.f, shi = 0.f;
    #pragma unroll
    for (int e = 0; e < 4; ++e) {
        elo[e] = (jc[e] <= rlo) ? __expf(vlo[e] - mlo) : 0.f;
        ehi[e] = (jc[e] <= rhi) ? __expf(vhi[e] - mhi) : 0.f;
        slo += elo[e]; shi += ehi[e];
    }
    slo += __shfl_xor_sync(0xffffffffu, slo, 1);
    slo += __shfl_xor_sync(0xffffffffu, slo, 2);
    shi += __shfl_xor_sync(0xffffffffu, shi, 1);
    shi += __shfl_xor_sync(0xffffffffu, shi, 2);
    const float ilo = 1.f / slo, ihi = 1.f / shi;

    // pack P into fp16 a-frags: reg0=(rlo, j c0..c0+1), reg1=(rhi, same),
    // reg2=(rlo, j+8), reg3=(rhi, j+8)
    uint32_t pa[4];
    __half2 h0 = __floats2half2_rn(elo[0] * ilo, elo[1] * ilo);
    __half2 h1 = __floats2half2_rn(ehi[0] * ihi, ehi[1] * ihi);
    __half2 h2 = __floats2half2_rn(elo[2] * ilo, elo[3] * ilo);
    __half2 h3 = __floats2half2_rn(ehi[2] * ihi, ehi[3] * ihi);
    pa[0] = *(uint32_t*)&h0; pa[1] = *(uint32_t*)&h1;
    pa[2] = *(uint32_t*)&h2; pa[3] = *(uint32_t*)&h3;

    // O = P * V^T-tiles (B-frags from V^T [64][VT_PITCH], plain ldmatrix)
    float oc[8][4];
    #pragma unroll
    for (int g = 0; g < 8; ++g)
        #pragma unroll
        for (int e = 0; e < 4; ++e) oc[g][e] = 0.f;

    #pragma unroll
    for (int dg = 0; dg < 4; ++dg) {
        uint32_t vq[4];
        ldmx4m(vb + (uint32_t)((dg * 16 + brb) * (VT_PITCH * 2)) + be * 16, vq);
        mma_f16(oc[2 * dg],     pa, vq);
        mma_f16(oc[2 * dg + 1], pa, vq + 2);
    }

    // store O to g_ah in final token order
    const int b = n >> 10;
    const int s = n & 1023;
    __half* olo = g_ah + (size_t)(b * 16384 + rlo * 1024 + s) * HIDDEN + hh * HD;
    __half* ohi = g_ah + (size_t)(b * 16384 + rhi * 1024 + s) * HIDDEN + hh * HD;
    #pragma unroll
    for (int g = 0; g < 8; ++g) {
        const int col = g * 8 + c0;
        *(__half2*)(olo + col) = __floats2half2_rn(oc[g][0], oc[g][1]);
        *(__half2*)(ohi + col) = __floats2half2_rn(oc[g][2], oc[g][3]);
    }
}

// ---------------------------------------------------------------------------
// Launch
// ---------------------------------------------------------------------------
extern "C" void kernel_launch(void* const* d_in, const int* in_sizes, int n_in,
                              void* d_out, int out_size)
{
    const float* x      = (const float*)d_in[0];
    const float* w_qkv  = (const float*)d_in[1];
    const float* w_out  = (const float*)d_in[2];
    const float* gamma  = (const float*)d_in[3];
    const float* beta   = (const float*)d_in[4];
    float* out = (float*)d_out;

    __half *xh, *wqh, *woh, *ah, *qkv;
    cudaGetSymbolAddress((void**)&xh,  g_xh);
    cudaGetSymbolAddress((void**)&wqh, g_wqh);
    cudaGetSymbolAddress((void**)&woh, g_woh);
    cudaGetSymbolAddress((void**)&ah,  g_ah);
    cudaGetSymbolAddress((void**)&qkv, g_qkv);

    cudaFuncSetAttribute(gemm_f16<__half>, cudaFuncAttributeMaxDynamicSharedMemorySize, GEMM_SMEM);
    cudaFuncSetAttribute(gemm_f16<float>,  cudaFuncAttributeMaxDynamicSharedMemorySize, GEMM_SMEM);

    // 1. LN + temporal transpose -> fp16
    ln_transpose_kernel<<<TOKENS, 256>>>(x, gamma, beta);

    // 1b. weight conversion
    w2h_kernel<<<(QKV_N * 1024 / 4 + 255) / 256, 256>>>(w_qkv, wqh, QKV_N * 1024);
    w2h_kernel<<<(HIDDEN * 1024 / 4 + 255) / 256, 256>>>(w_out, woh, HIDDEN * 1024);

    // 2. QKV projection: fp16 GEMM -> fp16
    {
        dim3 grid(QKV_N / 256, TOKENS / 128);
        gemm_f16<__half><<<grid, 256, GEMM_SMEM>>>(xh, wqh, qkv, QKV_N);
    }

    // 3. MMA-based RoPE + causal attention -> fp16 final order
    attn_kernel<<<NSEQ * NH / 4, 128>>>();

    // 4. Output projection -> d_out fp32
    {
        dim3 grid(HIDDEN / 256, TOKENS / 128);
        gemm_f16<float><<<grid, 256, GEMM_SMEM>>>(ah, woh, out, HIDDEN);
    }
}

// round 12
// speedup vs baseline: 1.4361x; 1.1460x over previous
#include <cuda_runtime.h>
#include <cuda_fp16.h>
#include <cstdint>

// ---------------------------------------------------------------------------
// Problem constants
// ---------------------------------------------------------------------------
#define HIDDEN   1024
#define FRAMES   16
#define SPATIAL  1024
#define BATCH    2
#define NSEQ     (BATCH*SPATIAL)        // 2048
#define TOKENS   (BATCH*FRAMES*SPATIAL) // 32768
#define NH       16
#define HD       64
#define QKV_N    3072

// ---------------------------------------------------------------------------
// Scratch
// ---------------------------------------------------------------------------
__device__ __half g_xh [(size_t)TOKENS * HIDDEN];  // LN'd + transposed, fp16
__device__ __half g_wqh[(size_t)QKV_N  * HIDDEN];  // w_qkv fp16
__device__ __half g_woh[(size_t)HIDDEN * HIDDEN];  // w_out fp16
__device__ __half g_ah [(size_t)TOKENS * HIDDEN];  // attn out fp16, final order
__device__ __half g_qkv[(size_t)TOKENS * QKV_N];   // QKV fp16

// ---------------------------------------------------------------------------
// PTX helpers
// ---------------------------------------------------------------------------
__device__ __forceinline__ uint32_t smem_u32(const void* p) {
    uint32_t a;
    asm("{ .reg .u64 t; cvta.to.shared.u64 t, %1; cvt.u32.u64 %0, t; }" : "=r"(a) : "l"(p));
    return a;
}
__device__ __forceinline__ void cp16(uint32_t dst, const void* src) {
    asm volatile("cp.async.cg.shared.global [%0], [%1], 16;" :: "r"(dst), "l"(src));
}
#define CP_COMMIT() asm volatile("cp.async.commit_group;" ::: "memory")
#define CP_WAIT1()  asm volatile("cp.async.wait_group 1;" ::: "memory")

__device__ __forceinline__ void ldmx4(uint32_t addr, uint32_t* r) {
    asm volatile("ldmatrix.sync.aligned.m8n8.x4.shared.b16 {%0,%1,%2,%3}, [%4];"
        : "=r"(r[0]), "=r"(r[1]), "=r"(r[2]), "=r"(r[3]) : "r"(addr));
}
// variant with memory clobber (attention: smem written by plain stores)
__device__ __forceinline__ void ldmx4m(uint32_t addr, uint32_t* r) {
    asm volatile("ldmatrix.sync.aligned.m8n8.x4.shared.b16 {%0,%1,%2,%3}, [%4];"
        : "=r"(r[0]), "=r"(r[1]), "=r"(r[2]), "=r"(r[3]) : "r"(addr) : "memory");
}
// non-volatile: pure register op, lets compiler interleave with LDSM
__device__ __forceinline__ void mma_f16(float* d, const uint32_t* a, const uint32_t* b) {
    asm("mma.sync.aligned.m16n8k16.row.col.f32.f16.f16.f32 "
        "{%0,%1,%2,%3},{%4,%5,%6,%7},{%8,%9},{%0,%1,%2,%3};"
        : "+f"(d[0]), "+f"(d[1]), "+f"(d[2]), "+f"(d[3])
        : "r"(a[0]), "r"(a[1]), "r"(a[2]), "r"(a[3]), "r"(b[0]), "r"(b[1]));
}

// byte offset of 16B chunk (r, ch) in a [rows x 128B] tile, SW128 swizzle
__device__ __forceinline__ uint32_t toff(int r, int ch) {
    return (uint32_t)(r * 128 + ((ch ^ (r & 7)) << 4));
}
// element pointer into a swizzled [16 x 64 half] tile
__device__ __forceinline__ __half* sptr(__half* base, int t, int d) {
    return (__half*)((char*)base + t * 128 + (((d >> 3) ^ (t & 7)) << 4) + (d & 7) * 2);
}

// ---------------------------------------------------------------------------
// Kernel 1: LayerNorm + temporal transpose -> fp16
// ---------------------------------------------------------------------------
__global__ __launch_bounds__(256) void ln_transpose_kernel(
    const float* __restrict__ x,
    const float* __restrict__ gamma,
    const float* __restrict__ beta)
{
    const int token = blockIdx.x;
    const int b  = token >> 14;
    const int sg = token & 16383;
    const int t  = sg >> 10;
    const int s  = sg & 1023;

    const int tid = threadIdx.x;
    const float4 v = ((const float4*)(x + (size_t)token * HIDDEN))[tid];

    float sum = v.x + v.y + v.z + v.w;
    float sq  = v.x*v.x + v.y*v.y + v.z*v.z + v.w*v.w;

    #pragma unroll
    for (int o = 16; o > 0; o >>= 1) {
        sum += __shfl_xor_sync(0xffffffffu, sum, o);
        sq  += __shfl_xor_sync(0xffffffffu, sq,  o);
    }
    __shared__ float s_sum[8], s_sq[8];
    __shared__ float s_mu, s_rstd;
    if ((tid & 31) == 0) { s_sum[tid >> 5] = sum; s_sq[tid >> 5] = sq; }
    __syncthreads();
    if (tid == 0) {
        float ts = 0.f, tq = 0.f;
        #pragma unroll
        for (int i = 0; i < 8; ++i) { ts += s_sum[i]; tq += s_sq[i]; }
        const float mu  = ts * (1.0f / HIDDEN);
        const float var = tq * (1.0f / HIDDEN) - mu * mu;
        s_mu = mu;
        s_rstd = rsqrtf(var + 1e-5f);
    }
    __syncthreads();
    const float mu = s_mu, rs = s_rstd;

    const float4 g  = ((const float4*)gamma)[tid];
    const float4 be = ((const float4*)beta)[tid];
    __half h[4];
    h[0] = __float2half_rn((v.x - mu) * rs * g.x + be.x);
    h[1] = __float2half_rn((v.y - mu) * rs * g.y + be.y);
    h[2] = __float2half_rn((v.z - mu) * rs * g.z + be.z);
    h[3] = __float2half_rn((v.w - mu) * rs * g.w + be.w);

    const size_t orow = (size_t)(b * SPATIAL + s) * FRAMES + t;
    *(uint2*)(g_xh + orow * HIDDEN + 4 * tid) = *(uint2*)h;
}

// ---------------------------------------------------------------------------
// fp32 -> fp16 weight convert
// ---------------------------------------------------------------------------
__global__ __launch_bounds__(256) void w2h_kernel(
    const float* __restrict__ w, __half* __restrict__ wh, int total)
{
    const int idx = (blockIdx.x * 256 + threadIdx.x) * 4;
    if (idx >= total) return;
    const float4 v = *(const float4*)(w + idx);
    __half h[4] = { __float2half_rn(v.x), __float2half_rn(v.y),
                    __float2half_rn(v.z), __float2half_rn(v.w) };
    *(uint2*)(wh + idx) = *(uint2*)h;
}

// ---------------------------------------------------------------------------
// fp16 mma.sync GEMM: C[M,N] = A[M,1024] * B[N,1024]^T
// BM=128, BN=128, BK=64; 128 threads (4 warps 2x2, warp tile 64x64);
// 3-stage cp.async ring, wait_group 1; TWO blocks per SM so one block's
// barrier stall is covered by the other block's MMAs.
// ---------------------------------------------------------------------------
#define KCH 16                    // 1024 / 64
#define A_TILE 16384              // 128 rows * 128B (64 halfs)
#define STG3   32768              // A + B per stage
#define GEMM_SMEM (3 * STG3)      // 98304

template <typename OutT>
__global__ __launch_bounds__(128, 2) void gemm_f16(
    const __half* __restrict__ A,
    const __half* __restrict__ B,
    OutT* __restrict__ C, int N)
{
    extern __shared__ __half smem[];
    const uint32_t base = smem_u32(smem);

    const int tid  = threadIdx.x;
    const int lane = tid & 31;
    const int wid  = tid >> 5;
    const int wm   = wid >> 1;         // 0..1  (64-row slab)
    const int wn   = wid & 1;          // 0..1  (64-col slab)
    const int bm   = blockIdx.y * 128;
    const int bn   = blockIdx.x * 128;

    // staging: 2048 16B chunks/stage, 16 per thread (8 A rows + 8 B rows)
    const int sr  = tid >> 3;          // 0..15
    const int sch = tid & 7;           // 16B chunk within 128B row
    const char* aSrc = (const char*)(A + (size_t)(bm + sr) * HIDDEN) + sch * 16;
    const char* bSrc = (const char*)(B + (size_t)(bn + sr) * HIDDEN) + sch * 16;
    const uint32_t aD = toff(sr, sch);            // + i*2048 for row sr+16i
    const uint32_t bD = A_TILE + toff(sr, sch);

    #define LOAD(c, so_abs)                                                     \
    {                                                                           \
        const int koff = (c) * 128;                                             \
        _Pragma("unroll")                                                       \
        for (int i = 0; i < 8; ++i)                                             \
            cp16((so_abs) + aD + i * 2048, aSrc + (size_t)i * (16 * HIDDEN * 2) + koff); \
        _Pragma("unroll")                                                       \
        for (int i = 0; i < 8; ++i)                                             \
            cp16((so_abs) + bD + i * 2048, bSrc + (size_t)i * (16 * HIDDEN * 2) + koff); \
    }

    // fragment lane coords
    const int arb = wm * 64 + (lane & 15);
    const int ae  = lane >> 4;
    const int brb = wn * 64 + (lane & 7) + ((lane >> 4) << 3);
    const int be  = (lane >> 3) & 1;

    float acc[4][8][4];
    #pragma unroll
    for (int i = 0; i < 4; ++i)
        #pragma unroll
        for (int j = 0; j < 8; ++j)
            #pragma unroll
            for (int e = 0; e < 4; ++e) acc[i][j][e] = 0.f;

    uint32_t aq[2][16], bq[2][16];

    // kk in 0..3 (k16 groups within BK=64)
    #define LDFRAG(buf, so, kk)                                                  \
    {                                                                            \
        _Pragma("unroll")                                                        \
        for (int mi = 0; mi < 4; ++mi)                                           \
            ldmx4((so) + toff(arb + mi * 16, (kk) * 2 + ae), &aq[buf][mi*4]);    \
        _Pragma("unroll")                                                        \
        for (int p = 0; p < 4; ++p)                                              \
            ldmx4((so) + A_TILE + toff(brb + p * 16, (kk) * 2 + be), &bq[buf][p*4]); \
    }

    #define MMAALL(buf)                                                          \
    {                                                                            \
        _Pragma("unroll")                                                        \
        for (int mi = 0; mi < 4; ++mi)                                           \
            _Pragma("unroll")                                                    \
            for (int p = 0; p < 4; ++p) {                                        \
                mma_f16(acc[mi][2*p],   &aq[buf][mi*4], &bq[buf][p*4]);          \
                mma_f16(acc[mi][2*p+1], &aq[buf][mi*4], &bq[buf][p*4+2]);        \
            }                                                                    \
    }

    // prologue: chunks 0,1 -> slots 0,1
    LOAD(0, base);        CP_COMMIT();
    LOAD(1, base + STG3); CP_COMMIT();

    uint32_t so_rd = base;
    uint32_t so_ld = base + 2 * STG3;

    #pragma unroll 1
    for (int c = 0; c < KCH; ++c) {
        CP_WAIT1();          // oldest group (chunk c) landed
        __syncthreads();     // all warps done reading slot so_ld's old data

        if (c + 2 < KCH) { LOAD(c + 2, so_ld); }
        CP_COMMIT();
        so_ld += STG3; if (so_ld > base + 2 * STG3) so_ld = base;

        LDFRAG(0, so_rd, 0);
        LDFRAG(1, so_rd, 1);
        MMAALL(0); LDFRAG(0, so_rd, 2);
        MMAALL(1); LDFRAG(1, so_rd, 3);
        MMAALL(0);
        MMAALL(1);

        so_rd += STG3; if (so_rd > base + 2 * STG3) so_rd = base;
    }
    #undef LOAD
    #undef LDFRAG
    #undef MMAALL

    // epilogue
    #pragma unroll
    for (int mi = 0; mi < 4; ++mi) {
        const int row = bm + wm * 64 + mi * 16 + (lane >> 2);
        #pragma unroll
        for (int nj = 0; nj < 8; ++nj) {
            const int col = bn + wn * 64 + nj * 8 + (lane & 3) * 2;
            if (sizeof(OutT) == 4) {
                float* Cf = (float*)C;
                *(float2*)(Cf + (size_t)row * N + col)       = make_float2(acc[mi][nj][0], acc[mi][nj][1]);
                *(float2*)(Cf + (size_t)(row + 8) * N + col) = make_float2(acc[mi][nj][2], acc[mi][nj][3]);
            } else {
                __half* Ch = (__half*)C;
                *(__half2*)(Ch + (size_t)row * N + col)       = __float22half2_rn(make_float2(acc[mi][nj][0], acc[mi][nj][1]));
                *(__half2*)(Ch + (size_t)(row + 8) * N + col) = __float22half2_rn(make_float2(acc[mi][nj][2], acc[mi][nj][3]));
            }
        }
    }
}

// ---------------------------------------------------------------------------
// Kernel 3: MMA-based RoPE + causal attention. One warp per (n, head).
// ---------------------------------------------------------------------------
#define VT_PITCH 24   // halfs per V^T row (48B, odd 16B multiple: conflict-free)

__global__ __launch_bounds__(128) void attn_kernel()
{
    const int wib  = threadIdx.x >> 5;
    const int lane = threadIdx.x & 31;
    const int nb = blockIdx.x * 4 + wib;   // 0..32767
    const int n  = nb >> 4;
    const int hh = nb & 15;

    __shared__ __align__(16) __half sQ [4][FRAMES * HD];        // swizzled 128B rows
    __shared__ __align__(16) __half sK [4][FRAMES * HD];
    __shared__ __align__(16) __half sVT[4][HD * VT_PITCH];      // V^T, 48B pitch

    __half* q  = sQ[wib];
    __half* k  = sK[wib];
    __half* vt = sVT[wib];

    const __half* gq = g_qkv + (size_t)n * FRAMES * QKV_N + hh * HD;

    // phase 1: cooperative copy Q,K (swizzled) + V transpose
    #pragma unroll
    for (int i = 0; i < 4; ++i) {
        const int id = lane + 32 * i;      // 0..127
        const int r  = id >> 3;            // frame 0..15
        const int ch = id & 7;             // 16B chunk (8 halfs of d)
        const char* rowp = (const char*)(gq + (size_t)r * QKV_N) + ch * 16;
        *(uint4*)((char*)q + toff(r, ch)) = *(const uint4*)(rowp);
        *(uint4*)((char*)k + toff(r, ch)) = *(const uint4*)(rowp + HIDDEN * 2);
        uint4 vv = *(const uint4*)(rowp + 2 * HIDDEN * 2);
        const __half* vh = (const __half*)&vv;
        #pragma unroll
        for (int e = 0; e < 8; ++e) vt[(ch * 8 + e) * VT_PITCH + r] = vh[e];
    }
    __syncwarp();

    // phase 2: RoPE in smem (Q scaled by 1/sqrt(64)=0.125)
    {
        const int t  = lane >> 1;
        const int pb = (lane & 1) * 16;
        #pragma unroll
        for (int p = 0; p < 16; ++p) {
            const int d = pb + p;          // 0..31
            const float inv = __expf(-(float)d * 0.28782313662425576f);
            float sn, cs;
            __sincosf((float)t * inv, &sn, &cs);
            __half *q1p = sptr(q, t, d), *q2p = sptr(q, t, d + 32);
            const float q1 = __half2float(*q1p), q2 = __half2float(*q2p);
            *q1p = __float2half_rn((q1 * cs - q2 * sn) * 0.125f);
            *q2p = __float2half_rn((q2 * cs + q1 * sn) * 0.125f);
            __half *k1p = sptr(k, t, d), *k2p = sptr(k, t, d + 32);
            const float k1 = __half2float(*k1p), k2 = __half2float(*k2p);
            *k1p = __float2half_rn(k1 * cs - k2 * sn);
            *k2p = __float2half_rn(k2 * cs + k1 * sn);
        }
    }
    __syncwarp();

    // S = Q * K^T
    const uint32_t qb = smem_u32(q), kb = smem_u32(k), vb = smem_u32(vt);
    const int arb = lane & 15;
    const int ae  = lane >> 4;
    const int brb = (lane & 7) + ((lane >> 4) << 3);
    const int be  = (lane >> 3) & 1;

    float s0[4] = {0.f, 0.f, 0.f, 0.f};    // cols 0-7
    float s1[4] = {0.f, 0.f, 0.f, 0.f};    // cols 8-15
    #pragma unroll
    for (int kg = 0; kg < 4; ++kg) {
        uint32_t aqf[4], bqf[4];
        ldmx4m(qb + toff(arb, kg * 2 + ae), aqf);
        ldmx4m(kb + toff(brb, kg * 2 + be), bqf);
        mma_f16(s0, aqf, bqf);
        mma_f16(s1, aqf, bqf + 2);
    }

    // softmax in c-frag registers
    const int rlo = lane >> 2, rhi = rlo + 8;
    const int c0  = 2 * (lane & 3);
    const int jc[4] = {c0, c0 + 1, c0 + 8, c0 + 9};
    float vlo[4] = {s0[0], s0[1], s1[0], s1[1]};
    float vhi[4] = {s0[2], s0[3], s1[2], s1[3]};

    float mlo = -1e30f, mhi = -1e30f;
    #pragma unroll
    for (int e = 0; e < 4; ++e) {
        if (jc[e] <= rlo) mlo = fmaxf(mlo, vlo[e]);
        if (jc[e] <= rhi) mhi = fmaxf(mhi, vhi[e]);
    }
    mlo = fmaxf(mlo, __shfl_xor_sync(0xffffffffu, mlo, 1));
    mlo = fmaxf(mlo, __shfl_xor_sync(0xffffffffu, mlo, 2));
    mhi = fmaxf(mhi, __shfl_xor_sync(0xffffffffu, mhi, 1));
    mhi = fmaxf(mhi, __shfl_xor_sync(0xffffffffu, mhi, 2));

    float elo[4], ehi[4], slo = 0.f, shi = 0.f;
    #pragma unroll
    for (int e = 0; e < 4; ++e) {
        elo[e] = (jc[e] <= rlo) ? __expf(vlo[e] - mlo) : 0.f;
        ehi[e] = (jc[e] <= rhi) ? __expf(vhi[e] - mhi) : 0.f;
        slo += elo[e]; shi += ehi[e];
    }
    slo += __shfl_xor_sync(0xffffffffu, slo, 1);
    slo += __shfl_xor_sync(0xffffffffu, slo, 2);
    shi += __shfl_xor_sync(0xffffffffu, shi, 1);
    shi += __shfl_xor_sync(0xffffffffu, shi, 2);
    const float ilo = 1.f / slo, ihi = 1.f / shi;

    // pack P into fp16 a-frags
    uint32_t pa[4];
    __half2 h0 = __floats2half2_rn(elo[0] * ilo, elo[1] * ilo);
    __half2 h1 = __floats2half2_rn(ehi[0] * ihi, ehi[1] * ihi);
    __half2 h2 = __floats2half2_rn(elo[2] * ilo, elo[3] * ilo);
    __half2 h3 = __floats2half2_rn(ehi[2] * ihi, ehi[3] * ihi);
    pa[0] = *(uint32_t*)&h0; pa[1] = *(uint32_t*)&h1;
    pa[2] = *(uint32_t*)&h2; pa[3] = *(uint32_t*)&h3;

    // O = P * V^T-tiles
    float oc[8][4];
    #pragma unroll
    for (int g = 0; g < 8; ++g)
        #pragma unroll
        for (int e = 0; e < 4; ++e) oc[g][e] = 0.f;

    #pragma unroll
    for (int dg = 0; dg < 4; ++dg) {
        uint32_t vq[4];
        ldmx4m(vb + (uint32_t)((dg * 16 + brb) * (VT_PITCH * 2)) + be * 16, vq);
        mma_f16(oc[2 * dg],     pa, vq);
        mma_f16(oc[2 * dg + 1], pa, vq + 2);
    }

    // store O to g_ah in final token order
    const int b = n >> 10;
    const int s = n & 1023;
    __half* olo = g_ah + (size_t)(b * 16384 + rlo * 1024 + s) * HIDDEN + hh * HD;
    __half* ohi = g_ah + (size_t)(b * 16384 + rhi * 1024 + s) * HIDDEN + hh * HD;
    #pragma unroll
    for (int g = 0; g < 8; ++g) {
        const int col = g * 8 + c0;
        *(__half2*)(olo + col) = __floats2half2_rn(oc[g][0], oc[g][1]);
        *(__half2*)(ohi + col) = __floats2half2_rn(oc[g][2], oc[g][3]);
    }
}

// ---------------------------------------------------------------------------
// Launch
// ---------------------------------------------------------------------------
extern "C" void kernel_launch(void* const* d_in, const int* in_sizes, int n_in,
                              void* d_out, int out_size)
{
    const float* x      = (const float*)d_in[0];
    const float* w_qkv  = (const float*)d_in[1];
    const float* w_out  = (const float*)d_in[2];
    const float* gamma  = (const float*)d_in[3];
    const float* beta   = (const float*)d_in[4];
    float* out = (float*)d_out;

    __half *xh, *wqh, *woh, *ah, *qkv;
    cudaGetSymbolAddress((void**)&xh,  g_xh);
    cudaGetSymbolAddress((void**)&wqh, g_wqh);
    cudaGetSymbolAddress((void**)&woh, g_woh);
    cudaGetSymbolAddress((void**)&ah,  g_ah);
    cudaGetSymbolAddress((void**)&qkv, g_qkv);

    cudaFuncSetAttribute(gemm_f16<__half>, cudaFuncAttributeMaxDynamicSharedMemorySize, GEMM_SMEM);
    cudaFuncSetAttribute(gemm_f16<float>,  cudaFuncAttributeMaxDynamicSharedMemorySize, GEMM_SMEM);

    // 1. LN + temporal transpose -> fp16
    ln_transpose_kernel<<<TOKENS, 256>>>(x, gamma, beta);

    // 1b. weight conversion
    w2h_kernel<<<(QKV_N * 1024 / 4 + 255) / 256, 256>>>(w_qkv, wqh, QKV_N * 1024);
    w2h_kernel<<<(HIDDEN * 1024 / 4 + 255) / 256, 256>>>(w_out, woh, HIDDEN * 1024);

    // 2. QKV projection: fp16 GEMM -> fp16
    {
        dim3 grid(QKV_N / 128, TOKENS / 128);
        gemm_f16<__half><<<grid, 128, GEMM_SMEM>>>(xh, wqh, qkv, QKV_N);
    }

    // 3. MMA-based RoPE + causal attention -> fp16 final order
    attn_kernel<<<NSEQ * NH / 4, 128>>>();

    // 4. Output projection -> d_out fp32
    {
        dim3 grid(HIDDEN / 128, TOKENS / 128);
        gemm_f16<float><<<grid, 128, GEMM_SMEM>>>(ah, woh, out, HIDDEN);
    }
}

// round 13
// speedup vs baseline: 1.4366x; 1.0003x over previous
#include <cuda_runtime.h>
#include <cuda_fp16.h>
#include <cstdint>

// ---------------------------------------------------------------------------
// Problem constants
// ---------------------------------------------------------------------------
#define HIDDEN   1024
#define FRAMES   16
#define SPATIAL  1024
#define BATCH    2
#define NSEQ     (BATCH*SPATIAL)        // 2048
#define TOKENS   (BATCH*FRAMES*SPATIAL) // 32768
#define NH       16
#define HD       64
#define QKV_N    3072

// ---------------------------------------------------------------------------
// Scratch
// ---------------------------------------------------------------------------
__device__ __half g_xh [(size_t)TOKENS * HIDDEN];  // LN'd + transposed, fp16
__device__ __half g_wqh[(size_t)QKV_N  * HIDDEN];  // w_qkv fp16
__device__ __half g_woh[(size_t)HIDDEN * HIDDEN];  // w_out fp16
__device__ __half g_ah [(size_t)TOKENS * HIDDEN];  // attn out fp16, final order
__device__ __half g_qkv[(size_t)TOKENS * QKV_N];   // QKV fp16

// ---------------------------------------------------------------------------
// PTX helpers
// ---------------------------------------------------------------------------
__device__ __forceinline__ uint32_t smem_u32(const void* p) {
    uint32_t a;
    asm("{ .reg .u64 t; cvta.to.shared.u64 t, %1; cvt.u32.u64 %0, t; }" : "=r"(a) : "l"(p));
    return a;
}
__device__ __forceinline__ void cp16(uint32_t dst, const void* src) {
    asm volatile("cp.async.cg.shared.global [%0], [%1], 16;" :: "r"(dst), "l"(src));
}
#define CP_COMMIT() asm volatile("cp.async.commit_group;" ::: "memory")
#define CP_WAIT1()  asm volatile("cp.async.wait_group 1;" ::: "memory")

__device__ __forceinline__ void ldmx4(uint32_t addr, uint32_t* r) {
    asm volatile("ldmatrix.sync.aligned.m8n8.x4.shared.b16 {%0,%1,%2,%3}, [%4];"
        : "=r"(r[0]), "=r"(r[1]), "=r"(r[2]), "=r"(r[3]) : "r"(addr));
}
// variant with memory clobber (attention: smem written by plain stores)
__device__ __forceinline__ void ldmx4m(uint32_t addr, uint32_t* r) {
    asm volatile("ldmatrix.sync.aligned.m8n8.x4.shared.b16 {%0,%1,%2,%3}, [%4];"
        : "=r"(r[0]), "=r"(r[1]), "=r"(r[2]), "=r"(r[3]) : "r"(addr) : "memory");
}
// non-volatile: pure register op, lets compiler interleave with LDSM
__device__ __forceinline__ void mma_f16(float* d, const uint32_t* a, const uint32_t* b) {
    asm("mma.sync.aligned.m16n8k16.row.col.f32.f16.f16.f32 "
        "{%0,%1,%2,%3},{%4,%5,%6,%7},{%8,%9},{%0,%1,%2,%3};"
        : "+f"(d[0]), "+f"(d[1]), "+f"(d[2]), "+f"(d[3])
        : "r"(a[0]), "r"(a[1]), "r"(a[2]), "r"(a[3]), "r"(b[0]), "r"(b[1]));
}

// byte offset of 16B chunk (r, ch) in a [rows x 128B] tile, SW128 swizzle
__device__ __forceinline__ uint32_t toff(int r, int ch) {
    return (uint32_t)(r * 128 + ((ch ^ (r & 7)) << 4));
}
// element pointer into a swizzled [16 x 64 half] tile
__device__ __forceinline__ __half* sptr(__half* base, int t, int d) {
    return (__half*)((char*)base + t * 128 + (((d >> 3) ^ (t & 7)) << 4) + (d & 7) * 2);
}

// ---------------------------------------------------------------------------
// Kernel 1: LayerNorm + temporal transpose -> fp16
// ---------------------------------------------------------------------------
__global__ __launch_bounds__(256) void ln_transpose_kernel(
    const float* __restrict__ x,
    const float* __restrict__ gamma,
    const float* __restrict__ beta)
{
    const int token = blockIdx.x;
    const int b  = token >> 14;
    const int sg = token & 16383;
    const int t  = sg >> 10;
    const int s  = sg & 1023;

    const int tid = threadIdx.x;
    const float4 v = ((const float4*)(x + (size_t)token * HIDDEN))[tid];

    float sum = v.x + v.y + v.z + v.w;
    float sq  = v.x*v.x + v.y*v.y + v.z*v.z + v.w*v.w;

    #pragma unroll
    for (int o = 16; o > 0; o >>= 1) {
        sum += __shfl_xor_sync(0xffffffffu, sum, o);
        sq  += __shfl_xor_sync(0xffffffffu, sq,  o);
    }
    __shared__ float s_sum[8], s_sq[8];
    __shared__ float s_mu, s_rstd;
    if ((tid & 31) == 0) { s_sum[tid >> 5] = sum; s_sq[tid >> 5] = sq; }
    __syncthreads();
    if (tid == 0) {
        float ts = 0.f, tq = 0.f;
        #pragma unroll
        for (int i = 0; i < 8; ++i) { ts += s_sum[i]; tq += s_sq[i]; }
        const float mu  = ts * (1.0f / HIDDEN);
        const float var = tq * (1.0f / HIDDEN) - mu * mu;
        s_mu = mu;
        s_rstd = rsqrtf(var + 1e-5f);
    }
    __syncthreads();
    const float mu = s_mu, rs = s_rstd;

    const float4 g  = ((const float4*)gamma)[tid];
    const float4 be = ((const float4*)beta)[tid];
    __half h[4];
    h[0] = __float2half_rn((v.x - mu) * rs * g.x + be.x);
    h[1] = __float2half_rn((v.y - mu) * rs * g.y + be.y);
    h[2] = __float2half_rn((v.z - mu) * rs * g.z + be.z);
    h[3] = __float2half_rn((v.w - mu) * rs * g.w + be.w);

    const size_t orow = (size_t)(b * SPATIAL + s) * FRAMES + t;
    *(uint2*)(g_xh + orow * HIDDEN + 4 * tid) = *(uint2*)h;
}

// ---------------------------------------------------------------------------
// fp32 -> fp16 convert for both weight matrices in one launch
// ---------------------------------------------------------------------------
#define WQ_TOT (QKV_N * 1024)     // 3145728
#define WO_TOT (HIDDEN * 1024)    // 1048576
__global__ __launch_bounds__(256) void w2h_both_kernel(
    const float* __restrict__ wq, __half* __restrict__ wqh,
    const float* __restrict__ wo, __half* __restrict__ woh)
{
    const int idx = (blockIdx.x * 256 + threadIdx.x) * 4;
    const float* src; __half* dst; int off;
    if (idx < WQ_TOT) { src = wq; dst = wqh; off = idx; }
    else               { src = wo; dst = woh; off = idx - WQ_TOT; }
    const float4 v = *(const float4*)(src + off);
    __half h[4] = { __float2half_rn(v.x), __float2half_rn(v.y),
                    __float2half_rn(v.z), __float2half_rn(v.w) };
    *(uint2*)(dst + off) = *(uint2*)h;
}

// ---------------------------------------------------------------------------
// fp16 mma.sync GEMM: C[M,N] = A[M,1024] * B[N,1024]^T
// BM=128, BN=128, BK=64; 128 threads (4 warps 2x2, warp tile 64x64);
// 3-stage cp.async ring, 2 blocks/SM; LOAD issued at chunk top, wait at
// chunk bottom + cross-chunk fragment prefetch.
// ---------------------------------------------------------------------------
#define KCH 16                    // 1024 / 64
#define A_TILE 16384              // 128 rows * 128B (64 halfs)
#define STG3   32768              // A + B per stage
#define GEMM_SMEM (3 * STG3)      // 98304

template <typename OutT>
__global__ __launch_bounds__(128, 2) void gemm_f16(
    const __half* __restrict__ A,
    const __half* __restrict__ B,
    OutT* __restrict__ C, int N)
{
    extern __shared__ __half smem[];
    const uint32_t base = smem_u32(smem);

    const int tid  = threadIdx.x;
    const int lane = tid & 31;
    const int wid  = tid >> 5;
    const int wm   = wid >> 1;         // 0..1  (64-row slab)
    const int wn   = wid & 1;          // 0..1  (64-col slab)
    const int bm   = blockIdx.y * 128;
    const int bn   = blockIdx.x * 128;

    // staging: 2048 16B chunks/stage, 16 per thread (8 A rows + 8 B rows)
    const int sr  = tid >> 3;          // 0..15
    const int sch = tid & 7;           // 16B chunk within 128B row
    const char* aSrc = (const char*)(A + (size_t)(bm + sr) * HIDDEN) + sch * 16;
    const char* bSrc = (const char*)(B + (size_t)(bn + sr) * HIDDEN) + sch * 16;
    const uint32_t aD = toff(sr, sch);            // + i*2048 for row sr+16i
    const uint32_t bD = A_TILE + toff(sr, sch);

    #define LOAD(c, so_abs)                                                     \
    {                                                                           \
        const int koff = (c) * 128;                                             \
        _Pragma("unroll")                                                       \
        for (int i = 0; i < 8; ++i)                                             \
            cp16((so_abs) + aD + i * 2048, aSrc + (size_t)i * (16 * HIDDEN * 2) + koff); \
        _Pragma("unroll")                                                       \
        for (int i = 0; i < 8; ++i)                                             \
            cp16((so_abs) + bD + i * 2048, bSrc + (size_t)i * (16 * HIDDEN * 2) + koff); \
    }

    // fragment lane coords
    const int arb = wm * 64 + (lane & 15);
    const int ae  = lane >> 4;
    const int brb = wn * 64 + (lane & 7) + ((lane >> 4) << 3);
    const int be  = (lane >> 3) & 1;

    float acc[4][8][4];
    #pragma unroll
    for (int i = 0; i < 4; ++i)
        #pragma unroll
        for (int j = 0; j < 8; ++j)
            #pragma unroll
            for (int e = 0; e < 4; ++e) acc[i][j][e] = 0.f;

    uint32_t aq[2][16], bq[2][16];

    // kk in 0..3 (k16 groups within BK=64)
    #define LDFRAG(buf, so, kk)                                                  \
    {                                                                            \
        _Pragma("unroll")                                                        \
        for (int mi = 0; mi < 4; ++mi)                                           \
            ldmx4((so) + toff(arb + mi * 16, (kk) * 2 + ae), &aq[buf][mi*4]);    \
        _Pragma("unroll")                                                        \
        for (int p = 0; p < 4; ++p)                                              \
            ldmx4((so) + A_TILE + toff(brb + p * 16, (kk) * 2 + be), &bq[buf][p*4]); \
    }

    #define MMAALL(buf)                                                          \
    {                                                                            \
        _Pragma("unroll")                                                        \
        for (int mi = 0; mi < 4; ++mi)                                           \
            _Pragma("unroll")                                                    \
            for (int p = 0; p < 4; ++p) {                                        \
                mma_f16(acc[mi][2*p],   &aq[buf][mi*4], &bq[buf][p*4]);          \
                mma_f16(acc[mi][2*p+1], &aq[buf][mi*4], &bq[buf][p*4+2]);        \
            }                                                                    \
    }

    // prologue: chunks 0,1 -> slots 0,1; wait chunk 0; prefetch its group 0
    LOAD(0, base);        CP_COMMIT();
    LOAD(1, base + STG3); CP_COMMIT();
    CP_WAIT1();
    __syncthreads();

    uint32_t so_rd = base;
    uint32_t so_ld = base + 2 * STG3;

    LDFRAG(0, so_rd, 0);

    #pragma unroll 1
    for (int c = 0; c < KCH; ++c) {
        // issue next stage's DMA at chunk top: slot so_ld was fully read in
        // chunk c-1 (barrier at its end covers all warps)
        if (c + 2 < KCH) { LOAD(c + 2, so_ld); }
        CP_COMMIT();
        so_ld += STG3; if (so_ld > base + 2 * STG3) so_ld = base;

        // aq/bq[0] hold chunk c group 0 (prefetched across the boundary)
        LDFRAG(1, so_rd, 1);
        MMAALL(0); LDFRAG(0, so_rd, 2);
        MMAALL(1); LDFRAG(1, so_rd, 3);
        MMAALL(0);
        MMAALL(1);

        so_rd += STG3; if (so_rd > base + 2 * STG3) so_rd = base;

        // boundary: chunk c+1 guaranteed landed (WAIT1 leaves only the group
        // committed THIS iteration pending); barrier gives cross-thread
        // visibility and closes the slot-reuse hazard; then prefetch group 0.
        if (c + 1 < KCH) {
            CP_WAIT1();
            __syncthreads();
            LDFRAG(0, so_rd, 0);
        }
    }
    #undef LOAD
    #undef LDFRAG
    #undef MMAALL

    // epilogue
    #pragma unroll
    for (int mi = 0; mi < 4; ++mi) {
        const int row = bm + wm * 64 + mi * 16 + (lane >> 2);
        #pragma unroll
        for (int nj = 0; nj < 8; ++nj) {
            const int col = bn + wn * 64 + nj * 8 + (lane & 3) * 2;
            if (sizeof(OutT) == 4) {
                float* Cf = (float*)C;
                *(float2*)(Cf + (size_t)row * N + col)       = make_float2(acc[mi][nj][0], acc[mi][nj][1]);
                *(float2*)(Cf + (size_t)(row + 8) * N + col) = make_float2(acc[mi][nj][2], acc[mi][nj][3]);
            } else {
                __half* Ch = (__half*)C;
                *(__half2*)(Ch + (size_t)row * N + col)       = __float22half2_rn(make_float2(acc[mi][nj][0], acc[mi][nj][1]));
                *(__half2*)(Ch + (size_t)(row + 8) * N + col) = __float22half2_rn(make_float2(acc[mi][nj][2], acc[mi][nj][3]));
            }
        }
    }
}

// ---------------------------------------------------------------------------
// Kernel 3: MMA-based RoPE + causal attention. One warp per (n, head).
// 256 threads = 8 warps per block; grid = NSEQ*NH/8 = 4096.
// ---------------------------------------------------------------------------
#define VT_PITCH 24   // halfs per V^T row (48B, odd 16B multiple: conflict-free)
#define AW 8          // warps per attention block

__global__ __launch_bounds__(32 * AW) void attn_kernel()
{
    const int wib  = threadIdx.x >> 5;
    const int lane = threadIdx.x & 31;
    const int nb = blockIdx.x * AW + wib;  // 0..32767
    const int n  = nb >> 4;
    const int hh = nb & 15;

    __shared__ __align__(16) __half sQ [AW][FRAMES * HD];       // swizzled 128B rows
    __shared__ __align__(16) __half sK [AW][FRAMES * HD];
    __shared__ __align__(16) __half sVT[AW][HD * VT_PITCH];     // V^T, 48B pitch

    __half* q  = sQ[wib];
    __half* k  = sK[wib];
    __half* vt = sVT[wib];

    const __half* gq = g_qkv + (size_t)n * FRAMES * QKV_N + hh * HD;

    // phase 1: cooperative copy Q,K (swizzled) + V transpose
    #pragma unroll
    for (int i = 0; i < 4; ++i) {
        const int id = lane + 32 * i;      // 0..127
        const int r  = id >> 3;            // frame 0..15
        const int ch = id & 7;             // 16B chunk (8 halfs of d)
        const char* rowp = (const char*)(gq + (size_t)r * QKV_N) + ch * 16;
        *(uint4*)((char*)q + toff(r, ch)) = *(const uint4*)(rowp);
        *(uint4*)((char*)k + toff(r, ch)) = *(const uint4*)(rowp + HIDDEN * 2);
        uint4 vv = *(const uint4*)(rowp + 2 * HIDDEN * 2);
        const __half* vh = (const __half*)&vv;
        #pragma unroll
        for (int e = 0; e < 8; ++e) vt[(ch * 8 + e) * VT_PITCH + r] = vh[e];
    }
    __syncwarp();

    // phase 2: RoPE in smem (Q scaled by 1/sqrt(64)=0.125)
    {
        const int t  = lane >> 1;
        const int pb = (lane & 1) * 16;
        #pragma unroll
        for (int p = 0; p < 16; ++p) {
            const int d = pb + p;          // 0..31
            const float inv = __expf(-(float)d * 0.28782313662425576f);
            float sn, cs;
            __sincosf((float)t * inv, &sn, &cs);
            __half *q1p = sptr(q, t, d), *q2p = sptr(q, t, d + 32);
            const float q1 = __half2float(*q1p), q2 = __half2float(*q2p);
            *q1p = __float2half_rn((q1 * cs - q2 * sn) * 0.125f);
            *q2p = __float2half_rn((q2 * cs + q1 * sn) * 0.125f);
            __half *k1p = sptr(k, t, d), *k2p = sptr(k, t, d + 32);
            const float k1 = __half2float(*k1p), k2 = __half2float(*k2p);
            *k1p = __float2half_rn(k1 * cs - k2 * sn);
            *k2p = __float2half_rn(k2 * cs + k1 * sn);
        }
    }
    __syncwarp();

    // S = Q * K^T
    const uint32_t qb = smem_u32(q), kb = smem_u32(k), vb = smem_u32(vt);
    const int arb = lane & 15;
    const int ae  = lane >> 4;
    const int brb = (lane & 7) + ((lane >> 4) << 3);
    const int be  = (lane >> 3) & 1;

    float s0[4] = {0.f, 0.f, 0.f, 0.f};    // cols 0-7
    float s1[4] = {0.f, 0.f, 0.f, 0.f};    // cols 8-15
    #pragma unroll
    for (int kg = 0; kg < 4; ++kg) {
        uint32_t aqf[4], bqf[4];
        ldmx4m(qb + toff(arb, kg * 2 + ae), aqf);
        ldmx4m(kb + toff(brb, kg * 2 + be), bqf);
        mma_f16(s0, aqf, bqf);
        mma_f16(s1, aqf, bqf + 2);
    }

    // softmax in c-frag registers
    const int rlo = lane >> 2, rhi = rlo + 8;
    const int c0  = 2 * (lane & 3);
    const int jc[4] = {c0, c0 + 1, c0 + 8, c0 + 9};
    float vlo[4] = {s0[0], s0[1], s1[0], s1[1]};
    float vhi[4] = {s0[2], s0[3], s1[2], s1[3]};

    float mlo = -1e30f, mhi = -1e30f;
    #pragma unroll
    for (int e = 0; e < 4; ++e) {
        if (jc[e] <= rlo) mlo = fmaxf(mlo, vlo[e]);
        if (jc[e] <= rhi) mhi = fmaxf(mhi, vhi[e]);
    }
    mlo = fmaxf(mlo, __shfl_xor_sync(0xffffffffu, mlo, 1));
    mlo = fmaxf(mlo, __shfl_xor_sync(0xffffffffu, mlo, 2));
    mhi = fmaxf(mhi, __shfl_xor_sync(0xffffffffu, mhi, 1));
    mhi = fmaxf(mhi, __shfl_xor_sync(0xffffffffu, mhi, 2));

    float elo[4], ehi[4], slo = 0.f, shi = 0.f;
    #pragma unroll
    for (int e = 0; e < 4; ++e) {
        elo[e] = (jc[e] <= rlo) ? __expf(vlo[e] - mlo) : 0.f;
        ehi[e] = (jc[e] <= rhi) ? __expf(vhi[e] - mhi) : 0.f;
        slo += elo[e]; shi += ehi[e];
    }
    slo += __shfl_xor_sync(0xffffffffu, slo, 1);
    slo += __shfl_xor_sync(0xffffffffu, slo, 2);
    shi += __shfl_xor_sync(0xffffffffu, shi, 1);
    shi += __shfl_xor_sync(0xffffffffu, shi, 2);
    const float ilo = 1.f / slo, ihi = 1.f / shi;

    // pack P into fp16 a-frags
    uint32_t pa[4];
    __half2 h0 = __floats2half2_rn(elo[0] * ilo, elo[1] * ilo);
    __half2 h1 = __floats2half2_rn(ehi[0] * ihi, ehi[1] * ihi);
    __half2 h2 = __floats2half2_rn(elo[2] * ilo, elo[3] * ilo);
    __half2 h3 = __floats2half2_rn(ehi[2] * ihi, ehi[3] * ihi);
    pa[0] = *(uint32_t*)&h0; pa[1] = *(uint32_t*)&h1;
    pa[2] = *(uint32_t*)&h2; pa[3] = *(uint32_t*)&h3;

    // O = P * V^T-tiles
    float oc[8][4];
    #pragma unroll
    for (int g = 0; g < 8; ++g)
        #pragma unroll
        for (int e = 0; e < 4; ++e) oc[g][e] = 0.f;

    #pragma unroll
    for (int dg = 0; dg < 4; ++dg) {
        uint32_t vq[4];
        ldmx4m(vb + (uint32_t)((dg * 16 + brb) * (VT_PITCH * 2)) + be * 16, vq);
        mma_f16(oc[2 * dg],     pa, vq);
        mma_f16(oc[2 * dg + 1], pa, vq + 2);
    }

    // store O to g_ah in final token order
    const int b = n >> 10;
    const int s = n & 1023;
    __half* olo = g_ah + (size_t)(b * 16384 + rlo * 1024 + s) * HIDDEN + hh * HD;
    __half* ohi = g_ah + (size_t)(b * 16384 + rhi * 1024 + s) * HIDDEN + hh * HD;
    #pragma unroll
    for (int g = 0; g < 8; ++g) {
        const int col = g * 8 + c0;
        *(__half2*)(olo + col) = __floats2half2_rn(oc[g][0], oc[g][1]);
        *(__half2*)(ohi + col) = __floats2half2_rn(oc[g][2], oc[g][3]);
    }
}

// ---------------------------------------------------------------------------
// Launch
// ---------------------------------------------------------------------------
extern "C" void kernel_launch(void* const* d_in, const int* in_sizes, int n_in,
                              void* d_out, int out_size)
{
    const float* x      = (const float*)d_in[0];
    const float* w_qkv  = (const float*)d_in[1];
    const float* w_out  = (const float*)d_in[2];
    const float* gamma  = (const float*)d_in[3];
    const float* beta   = (const float*)d_in[4];
    float* out = (float*)d_out;

    __half *xh, *wqh, *woh, *ah, *qkv;
    cudaGetSymbolAddress((void**)&xh,  g_xh);
    cudaGetSymbolAddress((void**)&wqh, g_wqh);
    cudaGetSymbolAddress((void**)&woh, g_woh);
    cudaGetSymbolAddress((void**)&ah,  g_ah);
    cudaGetSymbolAddress((void**)&qkv, g_qkv);

    cudaFuncSetAttribute(gemm_f16<__half>, cudaFuncAttributeMaxDynamicSharedMemorySize, GEMM_SMEM);
    cudaFuncSetAttribute(gemm_f16<float>,  cudaFuncAttributeMaxDynamicSharedMemorySize, GEMM_SMEM);

    // 1. LN + temporal transpose -> fp16
    ln_transpose_kernel<<<TOKENS, 256>>>(x, gamma, beta);

    // 1b. weight conversion (both matrices, one launch)
    w2h_both_kernel<<<(WQ_TOT + WO_TOT) / 4 / 256, 256>>>(w_qkv, wqh, w_out, woh);

    // 2. QKV projection: fp16 GEMM -> fp16
    {
        dim3 grid(QKV_N / 128, TOKENS / 128);
        gemm_f16<__half><<<grid, 128, GEMM_SMEM>>>(xh, wqh, qkv, QKV_N);
    }

    // 3. MMA-based RoPE + causal attention -> fp16 final order
    attn_kernel<<<NSEQ * NH / AW, 32 * AW>>>();

    // 4. Output projection -> d_out fp32
    {
        dim3 grid(HIDDEN / 128, TOKENS / 128);
        gemm_f16<float><<<grid, 128, GEMM_SMEM>>>(ah, woh, out, HIDDEN);
    }
}

// round 14
// speedup vs baseline: 1.5348x; 1.0684x over previous
#include <cuda_runtime.h>
#include <cuda_fp16.h>
#include <cstdint>

// ---------------------------------------------------------------------------
// Problem constants
// ---------------------------------------------------------------------------
#define HIDDEN   1024
#define FRAMES   16
#define SPATIAL  1024
#define BATCH    2
#define NSEQ     (BATCH*SPATIAL)        // 2048
#define TOKENS   (BATCH*FRAMES*SPATIAL) // 32768
#define NH       16
#define HD       64
#define QKV_N    3072

// ---------------------------------------------------------------------------
// Scratch
// ---------------------------------------------------------------------------
__device__ __half g_xh [(size_t)TOKENS * HIDDEN];  // LN'd + transposed, fp16
__device__ __half g_wqh[(size_t)QKV_N  * HIDDEN];  // w_qkv fp16
__device__ __half g_woh[(size_t)HIDDEN * HIDDEN];  // w_out fp16
__device__ __half g_ah [(size_t)TOKENS * HIDDEN];  // attn out fp16, final order
__device__ __half g_qkv[(size_t)TOKENS * QKV_N];   // QKV fp16
__device__ float2 g_rope[FRAMES * 32];             // (cos, sin) per (t, d)

// ---------------------------------------------------------------------------
// PTX helpers
// ---------------------------------------------------------------------------
__device__ __forceinline__ uint32_t smem_u32(const void* p) {
    uint32_t a;
    asm("{ .reg .u64 t; cvta.to.shared.u64 t, %1; cvt.u32.u64 %0, t; }" : "=r"(a) : "l"(p));
    return a;
}
__device__ __forceinline__ void cp16(uint32_t dst, const void* src) {
    asm volatile("cp.async.cg.shared.global [%0], [%1], 16;" :: "r"(dst), "l"(src));
}
#define CP_COMMIT() asm volatile("cp.async.commit_group;" ::: "memory")
#define CP_WAIT1()  asm volatile("cp.async.wait_group 1;" ::: "memory")

__device__ __forceinline__ void ldmx4(uint32_t addr, uint32_t* r) {
    asm volatile("ldmatrix.sync.aligned.m8n8.x4.shared.b16 {%0,%1,%2,%3}, [%4];"
        : "=r"(r[0]), "=r"(r[1]), "=r"(r[2]), "=r"(r[3]) : "r"(addr));
}
// memory-clobber variant (smem written by plain stores)
__device__ __forceinline__ void ldmx4m(uint32_t addr, uint32_t* r) {
    asm volatile("ldmatrix.sync.aligned.m8n8.x4.shared.b16 {%0,%1,%2,%3}, [%4];"
        : "=r"(r[0]), "=r"(r[1]), "=r"(r[2]), "=r"(r[3]) : "r"(addr) : "memory");
}
// transposed variant (V b-frags for P*V)
__device__ __forceinline__ void ldmx4t(uint32_t addr, uint32_t* r) {
    asm volatile("ldmatrix.sync.aligned.m8n8.x4.trans.shared.b16 {%0,%1,%2,%3}, [%4];"
        : "=r"(r[0]), "=r"(r[1]), "=r"(r[2]), "=r"(r[3]) : "r"(addr) : "memory");
}
// non-volatile: pure register op, lets compiler interleave with LDSM
__device__ __forceinline__ void mma_f16(float* d, const uint32_t* a, const uint32_t* b) {
    asm("mma.sync.aligned.m16n8k16.row.col.f32.f16.f16.f32 "
        "{%0,%1,%2,%3},{%4,%5,%6,%7},{%8,%9},{%0,%1,%2,%3};"
        : "+f"(d[0]), "+f"(d[1]), "+f"(d[2]), "+f"(d[3])
        : "r"(a[0]), "r"(a[1]), "r"(a[2]), "r"(a[3]), "r"(b[0]), "r"(b[1]));
}

// byte offset of 16B chunk (r, ch) in a [rows x 128B] tile, SW128 swizzle
__device__ __forceinline__ uint32_t toff(int r, int ch) {
    return (uint32_t)(r * 128 + ((ch ^ (r & 7)) << 4));
}

// ---------------------------------------------------------------------------
// Kernel 1: LayerNorm + temporal transpose -> fp16
// ---------------------------------------------------------------------------
__global__ __launch_bounds__(256) void ln_transpose_kernel(
    const float* __restrict__ x,
    const float* __restrict__ gamma,
    const float* __restrict__ beta)
{
    const int token = blockIdx.x;
    const int b  = token >> 14;
    const int sg = token & 16383;
    const int t  = sg >> 10;
    const int s  = sg & 1023;

    const int tid = threadIdx.x;
    const float4 v = ((const float4*)(x + (size_t)token * HIDDEN))[tid];

    float sum = v.x + v.y + v.z + v.w;
    float sq  = v.x*v.x + v.y*v.y + v.z*v.z + v.w*v.w;

    #pragma unroll
    for (int o = 16; o > 0; o >>= 1) {
        sum += __shfl_xor_sync(0xffffffffu, sum, o);
        sq  += __shfl_xor_sync(0xffffffffu, sq,  o);
    }
    __shared__ float s_sum[8], s_sq[8];
    __shared__ float s_mu, s_rstd;
    if ((tid & 31) == 0) { s_sum[tid >> 5] = sum; s_sq[tid >> 5] = sq; }
    __syncthreads();
    if (tid == 0) {
        float ts = 0.f, tq = 0.f;
        #pragma unroll
        for (int i = 0; i < 8; ++i) { ts += s_sum[i]; tq += s_sq[i]; }
        const float mu  = ts * (1.0f / HIDDEN);
        const float var = tq * (1.0f / HIDDEN) - mu * mu;
        s_mu = mu;
        s_rstd = rsqrtf(var + 1e-5f);
    }
    __syncthreads();
    const float mu = s_mu, rs = s_rstd;

    const float4 g  = ((const float4*)gamma)[tid];
    const float4 be = ((const float4*)beta)[tid];
    __half h[4];
    h[0] = __float2half_rn((v.x - mu) * rs * g.x + be.x);
    h[1] = __float2half_rn((v.y - mu) * rs * g.y + be.y);
    h[2] = __float2half_rn((v.z - mu) * rs * g.z + be.z);
    h[3] = __float2half_rn((v.w - mu) * rs * g.w + be.w);

    const size_t orow = (size_t)(b * SPATIAL + s) * FRAMES + t;
    *(uint2*)(g_xh + orow * HIDDEN + 4 * tid) = *(uint2*)h;
}

// ---------------------------------------------------------------------------
// fp32 -> fp16 convert for both weight matrices + RoPE table fill
// ---------------------------------------------------------------------------
#define WQ_TOT (QKV_N * 1024)     // 3145728
#define WO_TOT (HIDDEN * 1024)    // 1048576
__global__ __launch_bounds__(256) void w2h_both_kernel(
    const float* __restrict__ wq, __half* __restrict__ wqh,
    const float* __restrict__ wo, __half* __restrict__ woh)
{
    const int gid = blockIdx.x * 256 + threadIdx.x;

    // RoPE table: 512 entries (t 0..15, d 0..31)
    if (gid < FRAMES * 32) {
        const int t = gid >> 5;
        const int d = gid & 31;
        const float inv = __expf(-(float)d * 0.28782313662425576f);
        float sn, cs;
        __sincosf((float)t * inv, &sn, &cs);
        g_rope[gid] = make_float2(cs, sn);
    }

    const int idx = gid * 4;
    const float* src; __half* dst; int off;
    if (idx < WQ_TOT) { src = wq; dst = wqh; off = idx; }
    else               { src = wo; dst = woh; off = idx - WQ_TOT; }
    const float4 v = *(const float4*)(src + off);
    __half h[4] = { __float2half_rn(v.x), __float2half_rn(v.y),
                    __float2half_rn(v.z), __float2half_rn(v.w) };
    *(uint2*)(dst + off) = *(uint2*)h;
}

// ---------------------------------------------------------------------------
// fp16 mma.sync GEMM (unchanged from R13): BM=128, BN=128, BK=64; 128 thr;
// 3-stage cp.async ring, 2 blocks/SM, cross-chunk fragment prefetch.
// ---------------------------------------------------------------------------
#define KCH 16                    // 1024 / 64
#define A_TILE 16384              // 128 rows * 128B (64 halfs)
#define STG3   32768              // A + B per stage
#define GEMM_SMEM (3 * STG3)      // 98304

template <typename OutT>
__global__ __launch_bounds__(128, 2) void gemm_f16(
    const __half* __restrict__ A,
    const __half* __restrict__ B,
    OutT* __restrict__ C, int N)
{
    extern __shared__ __half smem[];
    const uint32_t base = smem_u32(smem);

    const int tid  = threadIdx.x;
    const int lane = tid & 31;
    const int wid  = tid >> 5;
    const int wm   = wid >> 1;         // 0..1  (64-row slab)
    const int wn   = wid & 1;          // 0..1  (64-col slab)
    const int bm   = blockIdx.y * 128;
    const int bn   = blockIdx.x * 128;

    const int sr  = tid >> 3;          // 0..15
    const int sch = tid & 7;           // 16B chunk within 128B row
    const char* aSrc = (const char*)(A + (size_t)(bm + sr) * HIDDEN) + sch * 16;
    const char* bSrc = (const char*)(B + (size_t)(bn + sr) * HIDDEN) + sch * 16;
    const uint32_t aD = toff(sr, sch);
    const uint32_t bD = A_TILE + toff(sr, sch);

    #define LOAD(c, so_abs)                                                     \
    {                                                                           \
        const int koff = (c) * 128;                                             \
        _Pragma("unroll")                                                       \
        for (int i = 0; i < 8; ++i)                                             \
            cp16((so_abs) + aD + i * 2048, aSrc + (size_t)i * (16 * HIDDEN * 2) + koff); \
        _Pragma("unroll")                                                       \
        for (int i = 0; i < 8; ++i)                                             \
            cp16((so_abs) + bD + i * 2048, bSrc + (size_t)i * (16 * HIDDEN * 2) + koff); \
    }

    const int arb = wm * 64 + (lane & 15);
    const int ae  = lane >> 4;
    const int brb = wn * 64 + (lane & 7) + ((lane >> 4) << 3);
    const int be  = (lane >> 3) & 1;

    float acc[4][8][4];
    #pragma unroll
    for (int i = 0; i < 4; ++i)
        #pragma unroll
        for (int j = 0; j < 8; ++j)
            #pragma unroll
            for (int e = 0; e < 4; ++e) acc[i][j][e] = 0.f;

    uint32_t aq[2][16], bq[2][16];

    #define LDFRAG(buf, so, kk)                                                  \
    {                                                                            \
        _Pragma("unroll")                                                        \
        for (int mi = 0; mi < 4; ++mi)                                           \
            ldmx4((so) + toff(arb + mi * 16, (kk) * 2 + ae), &aq[buf][mi*4]);    \
        _Pragma("unroll")                                                        \
        for (int p = 0; p < 4; ++p)                                              \
            ldmx4((so) + A_TILE + toff(brb + p * 16, (kk) * 2 + be), &bq[buf][p*4]); \
    }

    #define MMAALL(buf)                                                          \
    {                                                                            \
        _Pragma("unroll")                                                        \
        for (int mi = 0; mi < 4; ++mi)                                           \
            _Pragma("unroll")                                                    \
            for (int p = 0; p < 4; ++p) {                                        \
                mma_f16(acc[mi][2*p],   &aq[buf][mi*4], &bq[buf][p*4]);          \
                mma_f16(acc[mi][2*p+1], &aq[buf][mi*4], &bq[buf][p*4+2]);        \
            }                                                                    \
    }

    LOAD(0, base);        CP_COMMIT();
    LOAD(1, base + STG3); CP_COMMIT();
    CP_WAIT1();
    __syncthreads();

    uint32_t so_rd = base;
    uint32_t so_ld = base + 2 * STG3;

    LDFRAG(0, so_rd, 0);

    #pragma unroll 1
    for (int c = 0; c < KCH; ++c) {
        if (c + 2 < KCH) { LOAD(c + 2, so_ld); }
        CP_COMMIT();
        so_ld += STG3; if (so_ld > base + 2 * STG3) so_ld = base;

        LDFRAG(1, so_rd, 1);
        MMAALL(0); LDFRAG(0, so_rd, 2);
        MMAALL(1); LDFRAG(1, so_rd, 3);
        MMAALL(0);
        MMAALL(1);

        so_rd += STG3; if (so_rd > base + 2 * STG3) so_rd = base;

        if (c + 1 < KCH) {
            CP_WAIT1();
            __syncthreads();
            LDFRAG(0, so_rd, 0);
        }
    }
    #undef LOAD
    #undef LDFRAG
    #undef MMAALL

    #pragma unroll
    for (int mi = 0; mi < 4; ++mi) {
        const int row = bm + wm * 64 + mi * 16 + (lane >> 2);
        #pragma unroll
        for (int nj = 0; nj < 8; ++nj) {
            const int col = bn + wn * 64 + nj * 8 + (lane & 3) * 2;
            if (sizeof(OutT) == 4) {
                float* Cf = (float*)C;
                *(float2*)(Cf + (size_t)row * N + col)       = make_float2(acc[mi][nj][0], acc[mi][nj][1]);
                *(float2*)(Cf + (size_t)(row + 8) * N + col) = make_float2(acc[mi][nj][2], acc[mi][nj][3]);
            } else {
                __half* Ch = (__half*)C;
                *(__half2*)(Ch + (size_t)row * N + col)       = __float22half2_rn(make_float2(acc[mi][nj][0], acc[mi][nj][1]));
                *(__half2*)(Ch + (size_t)(row + 8) * N + col) = __float22half2_rn(make_float2(acc[mi][nj][2], acc[mi][nj][3]));
            }
        }
    }
}

// ---------------------------------------------------------------------------
// Kernel 3: MMA-based RoPE + causal attention. One warp per (n, head).
// RoPE fused into gmem->smem copy (table-driven); V stored like Q/K and
// consumed via ldmatrix.trans — no scalar smem traffic anywhere.
// ---------------------------------------------------------------------------
#define AW 8          // warps per attention block

__global__ __launch_bounds__(32 * AW) void attn_kernel()
{
    const int wib  = threadIdx.x >> 5;
    const int lane = threadIdx.x & 31;
    const int nb = blockIdx.x * AW + wib;  // 0..32767
    const int n  = nb >> 4;
    const int hh = nb & 15;

    __shared__ __align__(16) __half sQ[AW][FRAMES * HD];   // swizzled 128B rows
    __shared__ __align__(16) __half sK[AW][FRAMES * HD];
    __shared__ __align__(16) __half sV[AW][FRAMES * HD];

    __half* q = sQ[wib];
    __half* k = sK[wib];
    __half* v = sV[wib];

    const __half* gq = g_qkv + (size_t)n * FRAMES * QKV_N + hh * HD;

    // phase 1a: Q,K copy with fused RoPE. 64 items: (r, cp) — chunk cp pairs
    // with chunk cp+4 (d and d+32).
    #pragma unroll
    for (int i = 0; i < 2; ++i) {
        const int it = lane + 32 * i;      // 0..63
        const int r  = it >> 2;            // frame
        const int cp = it & 3;             // chunk pair index (d-lo chunk)
        const char* rowp = (const char*)(gq + (size_t)r * QKV_N);

        uint4 qlo = *(const uint4*)(rowp + cp * 16);
        uint4 qhi = *(const uint4*)(rowp + (cp + 4) * 16);
        uint4 klo = *(const uint4*)(rowp + HIDDEN * 2 + cp * 16);
        uint4 khi = *(const uint4*)(rowp + HIDDEN * 2 + (cp + 4) * 16);
        const __half* ql = (const __half*)&qlo; const __half* qh = (const __half*)&qhi;
        const __half* kl = (const __half*)&klo; const __half* kh = (const __half*)&khi;

        uint4 oql, oqh, okl, okh;
        __half* pql = (__half*)&oql; __half* pqh = (__half*)&oqh;
        __half* pkl = (__half*)&okl; __half* pkh = (__half*)&okh;
        const float2* rt = g_rope + r * 32 + cp * 8;
        #pragma unroll
        for (int e = 0; e < 8; ++e) {
            const float2 cs = rt[e];
            const float q1 = __half2float(ql[e]), q2 = __half2float(qh[e]);
            pql[e] = __float2half_rn((q1 * cs.x - q2 * cs.y) * 0.125f);
            pqh[e] = __float2half_rn((q2 * cs.x + q1 * cs.y) * 0.125f);
            const float k1 = __half2float(kl[e]), k2 = __half2float(kh[e]);
            pkl[e] = __float2half_rn(k1 * cs.x - k2 * cs.y);
            pkh[e] = __float2half_rn(k2 * cs.x + k1 * cs.y);
        }
        *(uint4*)((char*)q + toff(r, cp))     = oql;
        *(uint4*)((char*)q + toff(r, cp + 4)) = oqh;
        *(uint4*)((char*)k + toff(r, cp))     = okl;
        *(uint4*)((char*)k + toff(r, cp + 4)) = okh;
    }
    // phase 1b: V plain swizzled copy (consumed via ldmatrix.trans)
    #pragma unroll
    for (int i = 0; i < 4; ++i) {
        const int it = lane + 32 * i;      // 0..127
        const int r  = it >> 3;
        const int ch = it & 7;
        *(uint4*)((char*)v + toff(r, ch)) =
            *(const uint4*)((const char*)(gq + (size_t)r * QKV_N + 2 * HIDDEN) + ch * 16);
    }
    __syncwarp();

    // S = Q * K^T
    const uint32_t qb = smem_u32(q), kb = smem_u32(k), vb = smem_u32(v);
    const int arb = lane & 15;
    const int ae  = lane >> 4;
    const int brb = (lane & 7) + ((lane >> 4) << 3);
    const int be  = (lane >> 3) & 1;

    float s0[4] = {0.f, 0.f, 0.f, 0.f};    // cols 0-7
    float s1[4] = {0.f, 0.f, 0.f, 0.f};    // cols 8-15
    #pragma unroll
    for (int kg = 0; kg < 4; ++kg) {
        uint32_t aqf[4], bqf[4];
        ldmx4m(qb + toff(arb, kg * 2 + ae), aqf);
        ldmx4m(kb + toff(brb, kg * 2 + be), bqf);
        mma_f16(s0, aqf, bqf);
        mma_f16(s1, aqf, bqf + 2);
    }

    // softmax in c-frag registers
    const int rlo = lane >> 2, rhi = rlo + 8;
    const int c0  = 2 * (lane & 3);
    const int jc[4] = {c0, c0 + 1, c0 + 8, c0 + 9};
    float vlo[4] = {s0[0], s0[1], s1[0], s1[1]};
    float vhi[4] = {s0[2], s0[3], s1[2], s1[3]};

    float mlo = -1e30f, mhi = -1e30f;
    #pragma unroll
    for (int e = 0; e < 4; ++e) {
        if (jc[e] <= rlo) mlo = fmaxf(mlo, vlo[e]);
        if (jc[e] <= rhi) mhi = fmaxf(mhi, vhi[e]);
    }
    mlo = fmaxf(mlo, __shfl_xor_sync(0xffffffffu, mlo, 1));
    mlo = fmaxf(mlo, __shfl_xor_sync(0xffffffffu, mlo, 2));
    mhi = fmaxf(mhi, __shfl_xor_sync(0xffffffffu, mhi, 1));
    mhi = fmaxf(mhi, __shfl_xor_sync(0xffffffffu, mhi, 2));

    float elo[4], ehi[4], slo = 0.f, shi = 0.f;
    #pragma unroll
    for (int e = 0; e < 4; ++e) {
        elo[e] = (jc[e] <= rlo) ? __expf(vlo[e] - mlo) : 0.f;
        ehi[e] = (jc[e] <= rhi) ? __expf(vhi[e] - mhi) : 0.f;
        slo += elo[e]; shi += ehi[e];
    }
    slo += __shfl_xor_sync(0xffffffffu, slo, 1);
    slo += __shfl_xor_sync(0xffffffffu, slo, 2);
    shi += __shfl_xor_sync(0xffffffffu, shi, 1);
    shi += __shfl_xor_sync(0xffffffffu, shi, 2);
    const float ilo = 1.f / slo, ihi = 1.f / shi;

    // pack P into fp16 a-frags
    uint32_t pa[4];
    __half2 h0 = __floats2half2_rn(elo[0] * ilo, elo[1] * ilo);
    __half2 h1 = __floats2half2_rn(ehi[0] * ihi, ehi[1] * ihi);
    __half2 h2 = __floats2half2_rn(elo[2] * ilo, elo[3] * ilo);
    __half2 h3 = __floats2half2_rn(ehi[2] * ihi, ehi[3] * ihi);
    pa[0] = *(uint32_t*)&h0; pa[1] = *(uint32_t*)&h1;
    pa[2] = *(uint32_t*)&h2; pa[3] = *(uint32_t*)&h3;

    // O = P * V via ldmatrix.trans b-frags from row-major V tile:
    // lane addresses row t = lane&15, chunk ch = dg*2 + (lane>>4);
    // regs {0,1} cover k=0..15 x n=d0..d0+7, regs {2,3} the next 8 dims.
    float oc[8][4];
    #pragma unroll
    for (int g = 0; g < 8; ++g)
        #pragma unroll
        for (int e = 0; e < 4; ++e) oc[g][e] = 0.f;

    #pragma unroll
    for (int dg = 0; dg < 4; ++dg) {
        uint32_t vq[4];
        ldmx4t(vb + toff(lane & 15, dg * 2 + (lane >> 4)), vq);
        mma_f16(oc[2 * dg],     pa, vq);
        mma_f16(oc[2 * dg + 1], pa, vq + 2);
    }

    // store O to g_ah in final token order
    const int b = n >> 10;
    const int s = n & 1023;
    __half* olo = g_ah + (size_t)(b * 16384 + rlo * 1024 + s) * HIDDEN + hh * HD;
    __half* ohi = g_ah + (size_t)(b * 16384 + rhi * 1024 + s) * HIDDEN + hh * HD;
    #pragma unroll
    for (int g = 0; g < 8; ++g) {
        const int col = g * 8 + c0;
        *(__half2*)(olo + col) = __floats2half2_rn(oc[g][0], oc[g][1]);
        *(__half2*)(ohi + col) = __floats2half2_rn(oc[g][2], oc[g][3]);
    }
}

// ---------------------------------------------------------------------------
// Launch
// ---------------------------------------------------------------------------
extern "C" void kernel_launch(void* const* d_in, const int* in_sizes, int n_in,
                              void* d_out, int out_size)
{
    const float* x      = (const float*)d_in[0];
    const float* w_qkv  = (const float*)d_in[1];
    const float* w_out  = (const float*)d_in[2];
    const float* gamma  = (const float*)d_in[3];
    const float* beta   = (const float*)d_in[4];
    float* out = (float*)d_out;

    __half *xh, *wqh, *woh, *ah, *qkv;
    cudaGetSymbolAddress((void**)&xh,  g_xh);
    cudaGetSymbolAddress((void**)&wqh, g_wqh);
    cudaGetSymbolAddress((void**)&woh, g_woh);
    cudaGetSymbolAddress((void**)&ah,  g_ah);
    cudaGetSymbolAddress((void**)&qkv, g_qkv);

    cudaFuncSetAttribute(gemm_f16<__half>, cudaFuncAttributeMaxDynamicSharedMemorySize, GEMM_SMEM);
    cudaFuncSetAttribute(gemm_f16<float>,  cudaFuncAttributeMaxDynamicSharedMemorySize, GEMM_SMEM);

    // 1. LN + temporal transpose -> fp16
    ln_transpose_kernel<<<TOKENS, 256>>>(x, gamma, beta);

    // 1b. weight conversion + RoPE table (one launch)
    w2h_both_kernel<<<(WQ_TOT + WO_TOT) / 4 / 256, 256>>>(w_qkv, wqh, w_out, woh);

    // 2. QKV projection: fp16 GEMM -> fp16
    {
        dim3 grid(QKV_N / 128, TOKENS / 128);
        gemm_f16<__half><<<grid, 128, GEMM_SMEM>>>(xh, wqh, qkv, QKV_N);
    }

    // 3. MMA-based RoPE + causal attention -> fp16 final order
    attn_kernel<<<NSEQ * NH / AW, 32 * AW>>>();

    // 4. Output projection -> d_out fp32
    {
        dim3 grid(HIDDEN / 128, TOKENS / 128);
        gemm_f16<float><<<grid, 128, GEMM_SMEM>>>(ah, woh, out, HIDDEN);
    }
}